// round 2
// baseline (speedup 1.0000x reference)
#include <cuda_runtime.h>
#include <math.h>

// ---------------- scratch (device globals; no allocation allowed) ----------------
__device__ float g_h1[256*16*32*32];    // layer1 output [B,16,32,32]
__device__ float g_h2[256*32*32*32];    // layer2 output [B,32,32,32] == fc input
__device__ float g_part[16*256*1024];   // fc1 split-K partials
__device__ float g_fc1[256*1024];       // fc1 output (post relu)

// =================================================================================
// Fused ConvNN-branch attention layer.
// grid = B (256), block = 256 threads (one per token).
// Does: pixel_unshuffle gather -> q,k,v,local -> full sim + streaming top-9 ->
//       per-head softmax attention over 9 neighbors -> concat @ Wo + bo ->
//       pixel_shuffle scatter.
// =================================================================================
template<int CIN, int CU, int R, int D, int CO>
__global__ void __launch_bounds__(256, 1) attn_kernel(
    const float* __restrict__ X,
    const float* __restrict__ Wc, const float* __restrict__ Bc,
    const float* __restrict__ Wq, const float* __restrict__ Wk, const float* __restrict__ Wv,
    const float* __restrict__ Wo, const float* __restrict__ Bo,
    float* __restrict__ Y)
{
    constexpr int NTOK = 256;
    constexpr int NHEADS = 4;
    constexpr int DH = D / NHEADS;
    constexpr int KNN = 9;
    constexpr int DPAD = D + 4;       // pad so STS of k/v rows isn't bank-conflicted
    constexpr int COUT = CO / 4;

    extern __shared__ float smem[];
    float* sWc = smem;                      // CU*R
    float* sWq = sWc + CU*R;                // CU*D
    float* sWk = sWq + CU*D;                // CU*D
    float* sWv = sWk + CU*D;                // CU*D
    float* sWo = sWv + CU*D;                // (R+D)*CO
    float* sBc = sWo + (R+D)*CO;            // R
    float* sBo = sBc + R;                   // CO
    float* sK  = sBo + CO;                  // NTOK*DPAD
    float* sV  = sK + NTOK*DPAD;            // NTOK*DPAD

    const int b = blockIdx.x;
    const int n = threadIdx.x;

    // ---- cooperative weight staging ----
    for (int idx = n; idx < CU*R; idx += NTOK) sWc[idx] = Wc[idx];
    for (int idx = n; idx < CU*D; idx += NTOK) { sWq[idx]=Wq[idx]; sWk[idx]=Wk[idx]; sWv[idx]=Wv[idx]; }
    for (int idx = n; idx < (R+D)*CO; idx += NTOK) sWo[idx] = Wo[idx];
    if (n < R)  sBc[n] = Bc[n];
    if (n < CO) sBo[n] = Bo[n];
    __syncthreads();

    const int i = n >> 4;   // token spatial row (h=16)
    const int j = n & 15;   // token spatial col (w=16)

    // ---- phase B: token gather + q/k/v/local projections ----
    float q[D], ka[D], va[D], loc[R];
    #pragma unroll
    for (int dd = 0; dd < D; dd++) { q[dd]=0.f; ka[dd]=0.f; va[dd]=0.f; }
    #pragma unroll
    for (int rr = 0; rr < R; rr++) loc[rr] = sBc[rr];

    #pragma unroll 4
    for (int c = 0; c < CU; c++) {
        const int ch = c >> 2, si = (c >> 1) & 1, sj = c & 1;
        const float tv = X[((b*CIN + ch)*32 + 2*i + si)*32 + 2*j + sj];
        const float4* wq4 = reinterpret_cast<const float4*>(sWq + c*D);
        const float4* wk4 = reinterpret_cast<const float4*>(sWk + c*D);
        const float4* wv4 = reinterpret_cast<const float4*>(sWv + c*D);
        const float4* wc4 = reinterpret_cast<const float4*>(sWc + c*R);
        #pragma unroll
        for (int d4 = 0; d4 < D/4; d4++) {
            float4 w;
            w = wq4[d4]; q[4*d4]+=tv*w.x;  q[4*d4+1]+=tv*w.y;  q[4*d4+2]+=tv*w.z;  q[4*d4+3]+=tv*w.w;
            w = wk4[d4]; ka[4*d4]+=tv*w.x; ka[4*d4+1]+=tv*w.y; ka[4*d4+2]+=tv*w.z; ka[4*d4+3]+=tv*w.w;
            w = wv4[d4]; va[4*d4]+=tv*w.x; va[4*d4+1]+=tv*w.y; va[4*d4+2]+=tv*w.z; va[4*d4+3]+=tv*w.w;
        }
        #pragma unroll
        for (int r4 = 0; r4 < R/4; r4++) {
            float4 w = wc4[r4];
            loc[4*r4]+=tv*w.x; loc[4*r4+1]+=tv*w.y; loc[4*r4+2]+=tv*w.z; loc[4*r4+3]+=tv*w.w;
        }
    }
    #pragma unroll
    for (int rr = 0; rr < R; rr++) loc[rr] = fmaxf(loc[rr], 0.f);
    #pragma unroll
    for (int d4 = 0; d4 < D/4; d4++) {
        reinterpret_cast<float4*>(sK + n*DPAD)[d4] = make_float4(ka[4*d4],ka[4*d4+1],ka[4*d4+2],ka[4*d4+3]);
        reinterpret_cast<float4*>(sV + n*DPAD)[d4] = make_float4(va[4*d4],va[4*d4+1],va[4*d4+2],va[4*d4+3]);
    }
    __syncthreads();

    // ---- phase C: full-d sim over all tokens + streaming top-9 ----
    // strict '>' => on ties, the earlier index wins (matches jax.lax.top_k stable order)
    float topv[KNN]; int topi[KNN];
    #pragma unroll
    for (int kk = 0; kk < KNN; kk++) { topv[kk] = -1e30f; topi[kk] = 0; }

    for (int m = 0; m < NTOK; m++) {
        const float4* kp = reinterpret_cast<const float4*>(sK + m*DPAD);
        float dot = 0.f;
        #pragma unroll
        for (int d4 = 0; d4 < D/4; d4++) {
            float4 kv = kp[d4];
            dot += q[4*d4]*kv.x + q[4*d4+1]*kv.y + q[4*d4+2]*kv.z + q[4*d4+3]*kv.w;
        }
        if (dot > topv[KNN-1]) {
            topv[KNN-1] = dot; topi[KNN-1] = m;
            #pragma unroll
            for (int jj = KNN-1; jj > 0; --jj) {
                if (topv[jj] > topv[jj-1]) {
                    float tv_ = topv[jj]; topv[jj] = topv[jj-1]; topv[jj-1] = tv_;
                    int   ti_ = topi[jj]; topi[jj] = topi[jj-1]; topi[jj-1] = ti_;
                }
            }
        }
    }

    // ---- phase D: per-head softmax attention over the 9 neighbors ----
    const float scale = 1.0f / sqrtf((float)DH);
    float agg[D];
    #pragma unroll
    for (int h = 0; h < NHEADS; h++) {
        float lg[KNN];
        #pragma unroll
        for (int kk = 0; kk < KNN; kk++) {
            const float4* kr = reinterpret_cast<const float4*>(sK + topi[kk]*DPAD + h*DH);
            float s = 0.f;
            #pragma unroll
            for (int d4 = 0; d4 < DH/4; d4++) {
                float4 kv = kr[d4];
                s += q[h*DH+4*d4]*kv.x + q[h*DH+4*d4+1]*kv.y + q[h*DH+4*d4+2]*kv.z + q[h*DH+4*d4+3]*kv.w;
            }
            lg[kk] = s * scale;
        }
        float mx = lg[0];
        #pragma unroll
        for (int kk = 1; kk < KNN; kk++) mx = fmaxf(mx, lg[kk]);
        float den = 0.f;
        #pragma unroll
        for (int kk = 0; kk < KNN; kk++) { lg[kk] = expf(lg[kk] - mx); den += lg[kk]; }
        const float inv = 1.0f / den;

        float ah[DH];
        #pragma unroll
        for (int dd = 0; dd < DH; dd++) ah[dd] = 0.f;
        #pragma unroll
        for (int kk = 0; kk < KNN; kk++) {
            const float w = lg[kk];
            const float4* vr = reinterpret_cast<const float4*>(sV + topi[kk]*DPAD + h*DH);
            #pragma unroll
            for (int d4 = 0; d4 < DH/4; d4++) {
                float4 vv = vr[d4];
                ah[4*d4]+=w*vv.x; ah[4*d4+1]+=w*vv.y; ah[4*d4+2]+=w*vv.z; ah[4*d4+3]+=w*vv.w;
            }
        }
        #pragma unroll
        for (int dd = 0; dd < DH; dd++) agg[h*DH+dd] = ah[dd]*inv;
    }

    // ---- phase E: concat([local, agg]) @ Wo + bo, pixel_shuffle scatter ----
    #pragma unroll 1
    for (int cog = 0; cog < COUT; cog++) {
        float o0 = sBo[4*cog+0], o1 = sBo[4*cog+1], o2 = sBo[4*cog+2], o3 = sBo[4*cog+3];
        #pragma unroll
        for (int rr = 0; rr < R; rr++) {
            const float lv = loc[rr];
            const float4 w = reinterpret_cast<const float4*>(sWo + rr*CO)[cog];
            o0 += lv*w.x; o1 += lv*w.y; o2 += lv*w.z; o3 += lv*w.w;
        }
        #pragma unroll
        for (int dd = 0; dd < D; dd++) {
            const float av = agg[dd];
            const float4 w = reinterpret_cast<const float4*>(sWo + (R+dd)*CO)[cog];
            o0 += av*w.x; o1 += av*w.y; o2 += av*w.z; o3 += av*w.w;
        }
        // co = 4*cog + (si*2+sj)  ->  y[b, cog, 2i+si, 2j+sj]
        float* yb = Y + ((size_t)(b*COUT + cog)*32 + 2*i)*32 + 2*j;
        *reinterpret_cast<float2*>(yb)      = make_float2(o0, o1);
        *reinterpret_cast<float2*>(yb + 32) = make_float2(o2, o3);
    }
}

// =================================================================================
// fc1: C_part[s] = A[256,32768] @ W[32768,1024], split-K=16.
// 128x128 tile, 8x8 per thread, BK=16, single-stage smem with register prefetch.
// =================================================================================
__global__ void __launch_bounds__(256, 2) fc1_gemm(
    const float* __restrict__ A, const float* __restrict__ W, float* __restrict__ P)
{
    constexpr int BK = 16, KC = 2048, KT = 32768, NN = 1024;
    __shared__ float sA[BK][128];
    __shared__ float sB[BK][128];
    const int tid = threadIdx.x;
    const int m0 = blockIdx.y * 128, n0 = blockIdx.x * 128, k0 = blockIdx.z * KC;
    const int ar = tid >> 1, ac = (tid & 1) * 8;
    const int br = tid >> 4, bc = (tid & 15) * 4;
    const float* Ap = A + (size_t)(m0 + ar)*KT + k0 + ac;
    const float* Wp = W + (size_t)(k0 + br)*NN + n0 + bc;
    const int tm = (tid >> 4) * 8, tn = (tid & 15) * 8;

    float acc[8][8];
    #pragma unroll
    for (int ii = 0; ii < 8; ii++)
        #pragma unroll
        for (int jj = 0; jj < 8; jj++) acc[ii][jj] = 0.f;

    float4 a0 = *(const float4*)(Ap);
    float4 a1 = *(const float4*)(Ap + 4);
    float4 b0 = *(const float4*)(Wp);
    float4 b1 = *(const float4*)(Wp + 64);

    for (int kt = 0; kt < KC; kt += BK) {
        sA[ac+0][ar]=a0.x; sA[ac+1][ar]=a0.y; sA[ac+2][ar]=a0.z; sA[ac+3][ar]=a0.w;
        sA[ac+4][ar]=a1.x; sA[ac+5][ar]=a1.y; sA[ac+6][ar]=a1.z; sA[ac+7][ar]=a1.w;
        *(float4*)&sB[br][bc]      = b0;
        *(float4*)&sB[br][bc + 64] = b1;
        __syncthreads();
        if (kt + BK < KC) {  // prefetch next tile while computing this one
            a0 = *(const float4*)(Ap + kt + BK);
            a1 = *(const float4*)(Ap + kt + BK + 4);
            b0 = *(const float4*)(Wp + (size_t)(kt + BK)*NN);
            b1 = *(const float4*)(Wp + (size_t)(kt + BK)*NN + 64);
        }
        #pragma unroll
        for (int k = 0; k < BK; k++) {
            float av[8], bv[8];
            *(float4*)(av)     = *(const float4*)&sA[k][tm];
            *(float4*)(av + 4) = *(const float4*)&sA[k][tm + 4];
            *(float4*)(bv)     = *(const float4*)&sB[k][tn];
            *(float4*)(bv + 4) = *(const float4*)&sB[k][tn + 4];
            #pragma unroll
            for (int ii = 0; ii < 8; ii++)
                #pragma unroll
                for (int jj = 0; jj < 8; jj++)
                    acc[ii][jj] += av[ii] * bv[jj];
        }
        __syncthreads();
    }
    float* Pp = P + (size_t)blockIdx.z * (256*1024);
    #pragma unroll
    for (int ii = 0; ii < 8; ii++) {
        float* row = Pp + (size_t)(m0 + tm + ii)*NN + n0 + tn;
        *(float4*)(row)     = make_float4(acc[ii][0],acc[ii][1],acc[ii][2],acc[ii][3]);
        *(float4*)(row + 4) = make_float4(acc[ii][4],acc[ii][5],acc[ii][6],acc[ii][7]);
    }
}

// fc1 partial reduction + bias + relu
__global__ void fc1_reduce(const float* __restrict__ P, const float* __restrict__ Bb,
                           float* __restrict__ O)
{
    const int idx = blockIdx.x * blockDim.x + threadIdx.x;   // 262144 total
    float s = Bb[idx & 1023];
    #pragma unroll
    for (int sp = 0; sp < 16; sp++) s += P[sp*262144 + idx];
    O[idx] = fmaxf(s, 0.f);
}

// fc2: [256,1024] @ [1024,10] + b, one block per batch row.
__global__ void fc2_kernel(const float* __restrict__ H, const float* __restrict__ W,
                           const float* __restrict__ Bb, float* __restrict__ out)
{
    const int b = blockIdx.x, tid = threadIdx.x;
    float acc[10];
    #pragma unroll
    for (int o = 0; o < 10; o++) acc[o] = 0.f;
    for (int k = tid; k < 1024; k += 128) {
        const float hv = H[b*1024 + k];
        const float* wr = W + k*10;
        #pragma unroll
        for (int o = 0; o < 10; o++) acc[o] += hv * wr[o];
    }
    __shared__ float red[4][10];
    #pragma unroll
    for (int o = 0; o < 10; o++) {
        #pragma unroll
        for (int off = 16; off; off >>= 1)
            acc[o] += __shfl_down_sync(0xffffffffu, acc[o], off);
    }
    if ((tid & 31) == 0) {
        #pragma unroll
        for (int o = 0; o < 10; o++) red[tid >> 5][o] = acc[o];
    }
    __syncthreads();
    if (tid < 10)
        out[b*10 + tid] = Bb[tid] + red[0][tid] + red[1][tid] + red[2][tid] + red[3][tid];
}

// =================================================================================
extern "C" void kernel_launch(void* const* d_in, const int* in_sizes, int n_in,
                              void* d_out, int out_size)
{
    const float* x    = (const float*)d_in[0];
    const float* w1c  = (const float*)d_in[1];
    const float* b1c  = (const float*)d_in[2];
    const float* w1q  = (const float*)d_in[3];
    const float* w1k  = (const float*)d_in[4];
    const float* w1v  = (const float*)d_in[5];
    const float* w1o  = (const float*)d_in[6];
    const float* b1o  = (const float*)d_in[7];
    const float* w2c  = (const float*)d_in[8];
    const float* b2c  = (const float*)d_in[9];
    const float* w2q  = (const float*)d_in[10];
    const float* w2k  = (const float*)d_in[11];
    const float* w2v  = (const float*)d_in[12];
    const float* w2o  = (const float*)d_in[13];
    const float* b2o  = (const float*)d_in[14];
    const float* fc1w = (const float*)d_in[15];
    const float* fc1b = (const float*)d_in[16];
    const float* fc2w = (const float*)d_in[17];
    const float* fc2b = (const float*)d_in[18];
    float* out = (float*)d_out;

    float *h1, *h2, *part, *fch;
    cudaGetSymbolAddress((void**)&h1,   g_h1);
    cudaGetSymbolAddress((void**)&h2,   g_h2);
    cudaGetSymbolAddress((void**)&part, g_part);
    cudaGetSymbolAddress((void**)&fch,  g_fc1);

    // dynamic smem sizes (floats): weights + biases + padded K/V token caches
    const int SM1 = (12*16 + 3*12*16 + (16+16)*64 + 16 + 64  + 2*256*(16+4)) * 4;
    const int SM2 = (64*32 + 3*64*32 + (32+32)*128 + 32 + 128 + 2*256*(32+4)) * 4;

    cudaFuncSetAttribute(attn_kernel<3,12,16,16,64>,
                         cudaFuncAttributeMaxDynamicSharedMemorySize, SM1);
    cudaFuncSetAttribute(attn_kernel<16,64,32,32,128>,
                         cudaFuncAttributeMaxDynamicSharedMemorySize, SM2);

    attn_kernel<3,12,16,16,64><<<256, 256, SM1>>>(x,  w1c, b1c, w1q, w1k, w1v, w1o, b1o, h1);
    attn_kernel<16,64,32,32,128><<<256, 256, SM2>>>(h1, w2c, b2c, w2q, w2k, w2v, w2o, b2o, h2);

    fc1_gemm<<<dim3(8, 2, 16), 256>>>(h2, fc1w, part);
    fc1_reduce<<<1024, 256>>>(part, fc1b, fch);
    fc2_kernel<<<256, 128>>>(fch, fc2w, fc2b, out);
}

// round 7
// speedup vs baseline: 1.3059x; 1.3059x over previous
#include <cuda_runtime.h>
#include <cuda_bf16.h>
#include <cstdint>
#include <stdint.h>
#include <math.h>

// ---------------- scratch (device globals; no allocation allowed) ----------------
__device__ float g_h1[256*16*32*32];            // layer1 output [B,16,32,32]
__device__ __nv_bfloat16 g_Ahi[256*32768];      // fc input, bf16 hi
__device__ __nv_bfloat16 g_Alo[256*32768];      // fc input, bf16 lo residual
__device__ __nv_bfloat16 g_Whi[1024ull*32768];  // fc1 weight TRANSPOSED [N,K], bf16 hi
__device__ __nv_bfloat16 g_Wlo[1024ull*32768];  // fc1 weight TRANSPOSED [N,K], bf16 lo
__device__ float g_part[16*256*1024];           // fc1 split-K partials
__device__ float g_fc1[256*1024];               // fc1 output (post relu)

// =================================================================================
// Fused ConvNN-branch attention layer. grid = B, block = 256 (one thread/token).
// If Ahi/Alo non-null (layer 2), emits bf16 hi/lo split of output instead of fp32.
// =================================================================================
template<int CIN, int CU, int R, int D, int CO>
__global__ void __launch_bounds__(256, 1) attn_kernel(
    const float* __restrict__ X,
    const float* __restrict__ Wc, const float* __restrict__ Bc,
    const float* __restrict__ Wq, const float* __restrict__ Wk, const float* __restrict__ Wv,
    const float* __restrict__ Wo, const float* __restrict__ Bo,
    float* __restrict__ Y, __nv_bfloat16* __restrict__ Ahi, __nv_bfloat16* __restrict__ Alo)
{
    constexpr int NTOK = 256;
    constexpr int NHEADS = 4;
    constexpr int DH = D / NHEADS;
    constexpr int KNN = 9;
    constexpr int DPAD = D + 4;
    constexpr int COUT = CO / 4;

    extern __shared__ float smem[];
    float* sWc = smem;
    float* sWq = sWc + CU*R;
    float* sWk = sWq + CU*D;
    float* sWv = sWk + CU*D;
    float* sWo = sWv + CU*D;
    float* sBc = sWo + (R+D)*CO;
    float* sBo = sBc + R;
    float* sK  = sBo + CO;
    float* sV  = sK + NTOK*DPAD;

    const int b = blockIdx.x;
    const int n = threadIdx.x;

    for (int idx = n; idx < CU*R; idx += NTOK) sWc[idx] = Wc[idx];
    for (int idx = n; idx < CU*D; idx += NTOK) { sWq[idx]=Wq[idx]; sWk[idx]=Wk[idx]; sWv[idx]=Wv[idx]; }
    for (int idx = n; idx < (R+D)*CO; idx += NTOK) sWo[idx] = Wo[idx];
    if (n < R)  sBc[n] = Bc[n];
    if (n < CO) sBo[n] = Bo[n];
    __syncthreads();

    const int i = n >> 4;
    const int j = n & 15;

    float q[D], ka[D], va[D], loc[R];
    #pragma unroll
    for (int dd = 0; dd < D; dd++) { q[dd]=0.f; ka[dd]=0.f; va[dd]=0.f; }
    #pragma unroll
    for (int rr = 0; rr < R; rr++) loc[rr] = sBc[rr];

    #pragma unroll 4
    for (int c = 0; c < CU; c++) {
        const int ch = c >> 2, si = (c >> 1) & 1, sj = c & 1;
        const float tv = X[((b*CIN + ch)*32 + 2*i + si)*32 + 2*j + sj];
        const float4* wq4 = reinterpret_cast<const float4*>(sWq + c*D);
        const float4* wk4 = reinterpret_cast<const float4*>(sWk + c*D);
        const float4* wv4 = reinterpret_cast<const float4*>(sWv + c*D);
        const float4* wc4 = reinterpret_cast<const float4*>(sWc + c*R);
        #pragma unroll
        for (int d4 = 0; d4 < D/4; d4++) {
            float4 w;
            w = wq4[d4]; q[4*d4]+=tv*w.x;  q[4*d4+1]+=tv*w.y;  q[4*d4+2]+=tv*w.z;  q[4*d4+3]+=tv*w.w;
            w = wk4[d4]; ka[4*d4]+=tv*w.x; ka[4*d4+1]+=tv*w.y; ka[4*d4+2]+=tv*w.z; ka[4*d4+3]+=tv*w.w;
            w = wv4[d4]; va[4*d4]+=tv*w.x; va[4*d4+1]+=tv*w.y; va[4*d4+2]+=tv*w.z; va[4*d4+3]+=tv*w.w;
        }
        #pragma unroll
        for (int r4 = 0; r4 < R/4; r4++) {
            float4 w = wc4[r4];
            loc[4*r4]+=tv*w.x; loc[4*r4+1]+=tv*w.y; loc[4*r4+2]+=tv*w.z; loc[4*r4+3]+=tv*w.w;
        }
    }
    #pragma unroll
    for (int rr = 0; rr < R; rr++) loc[rr] = fmaxf(loc[rr], 0.f);
    #pragma unroll
    for (int d4 = 0; d4 < D/4; d4++) {
        reinterpret_cast<float4*>(sK + n*DPAD)[d4] = make_float4(ka[4*d4],ka[4*d4+1],ka[4*d4+2],ka[4*d4+3]);
        reinterpret_cast<float4*>(sV + n*DPAD)[d4] = make_float4(va[4*d4],va[4*d4+1],va[4*d4+2],va[4*d4+3]);
    }
    __syncthreads();

    float topv[KNN]; int topi[KNN];
    #pragma unroll
    for (int kk = 0; kk < KNN; kk++) { topv[kk] = -1e30f; topi[kk] = 0; }

    for (int m = 0; m < NTOK; m++) {
        const float4* kp = reinterpret_cast<const float4*>(sK + m*DPAD);
        float dot = 0.f;
        #pragma unroll
        for (int d4 = 0; d4 < D/4; d4++) {
            float4 kv = kp[d4];
            dot += q[4*d4]*kv.x + q[4*d4+1]*kv.y + q[4*d4+2]*kv.z + q[4*d4+3]*kv.w;
        }
        if (dot > topv[KNN-1]) {
            topv[KNN-1] = dot; topi[KNN-1] = m;
            #pragma unroll
            for (int jj = KNN-1; jj > 0; --jj) {
                if (topv[jj] > topv[jj-1]) {
                    float tv_ = topv[jj]; topv[jj] = topv[jj-1]; topv[jj-1] = tv_;
                    int   ti_ = topi[jj]; topi[jj] = topi[jj-1]; topi[jj-1] = ti_;
                }
            }
        }
    }

    const float scale = 1.0f / sqrtf((float)DH);
    float agg[D];
    #pragma unroll
    for (int h = 0; h < NHEADS; h++) {
        float lg[KNN];
        #pragma unroll
        for (int kk = 0; kk < KNN; kk++) {
            const float4* kr = reinterpret_cast<const float4*>(sK + topi[kk]*DPAD + h*DH);
            float s = 0.f;
            #pragma unroll
            for (int d4 = 0; d4 < DH/4; d4++) {
                float4 kv = kr[d4];
                s += q[h*DH+4*d4]*kv.x + q[h*DH+4*d4+1]*kv.y + q[h*DH+4*d4+2]*kv.z + q[h*DH+4*d4+3]*kv.w;
            }
            lg[kk] = s * scale;
        }
        float mx = lg[0];
        #pragma unroll
        for (int kk = 1; kk < KNN; kk++) mx = fmaxf(mx, lg[kk]);
        float den = 0.f;
        #pragma unroll
        for (int kk = 0; kk < KNN; kk++) { lg[kk] = expf(lg[kk] - mx); den += lg[kk]; }
        const float inv = 1.0f / den;

        float ah[DH];
        #pragma unroll
        for (int dd = 0; dd < DH; dd++) ah[dd] = 0.f;
        #pragma unroll
        for (int kk = 0; kk < KNN; kk++) {
            const float w = lg[kk];
            const float4* vr = reinterpret_cast<const float4*>(sV + topi[kk]*DPAD + h*DH);
            #pragma unroll
            for (int d4 = 0; d4 < DH/4; d4++) {
                float4 vv = vr[d4];
                ah[4*d4]+=w*vv.x; ah[4*d4+1]+=w*vv.y; ah[4*d4+2]+=w*vv.z; ah[4*d4+3]+=w*vv.w;
            }
        }
        #pragma unroll
        for (int dd = 0; dd < DH; dd++) agg[h*DH+dd] = ah[dd]*inv;
    }

    #pragma unroll 1
    for (int cog = 0; cog < COUT; cog++) {
        float o0 = sBo[4*cog+0], o1 = sBo[4*cog+1], o2 = sBo[4*cog+2], o3 = sBo[4*cog+3];
        #pragma unroll
        for (int rr = 0; rr < R; rr++) {
            const float lv = loc[rr];
            const float4 w = reinterpret_cast<const float4*>(sWo + rr*CO)[cog];
            o0 += lv*w.x; o1 += lv*w.y; o2 += lv*w.z; o3 += lv*w.w;
        }
        #pragma unroll
        for (int dd = 0; dd < D; dd++) {
            const float av = agg[dd];
            const float4 w = reinterpret_cast<const float4*>(sWo + (R+dd)*CO)[cog];
            o0 += av*w.x; o1 += av*w.y; o2 += av*w.z; o3 += av*w.w;
        }
        if (Ahi) {
            // flat fc-input index: f = cog*1024 + (2i+si)*32 + (2j+sj)
            const size_t base = (size_t)b*32768 + (size_t)cog*1024 + (size_t)(2*i)*32 + 2*j;
            __nv_bfloat16 h0=__float2bfloat16_rn(o0), h1=__float2bfloat16_rn(o1);
            __nv_bfloat16 h2=__float2bfloat16_rn(o2), h3=__float2bfloat16_rn(o3);
            __nv_bfloat16 l0=__float2bfloat16_rn(o0-__bfloat162float(h0));
            __nv_bfloat16 l1=__float2bfloat16_rn(o1-__bfloat162float(h1));
            __nv_bfloat16 l2=__float2bfloat16_rn(o2-__bfloat162float(h2));
            __nv_bfloat16 l3=__float2bfloat16_rn(o3-__bfloat162float(h3));
            __nv_bfloat162 ph; ph.x=h0; ph.y=h1;
            __nv_bfloat162 pl; pl.x=l0; pl.y=l1;
            *reinterpret_cast<__nv_bfloat162*>(Ahi + base) = ph;
            *reinterpret_cast<__nv_bfloat162*>(Alo + base) = pl;
            ph.x=h2; ph.y=h3; pl.x=l2; pl.y=l3;
            *reinterpret_cast<__nv_bfloat162*>(Ahi + base + 32) = ph;
            *reinterpret_cast<__nv_bfloat162*>(Alo + base + 32) = pl;
        } else {
            float* yb = Y + ((size_t)(b*COUT + cog)*32 + 2*i)*32 + 2*j;
            *reinterpret_cast<float2*>(yb)      = make_float2(o0, o1);
            *reinterpret_cast<float2*>(yb + 32) = make_float2(o2, o3);
        }
    }
}

// =================================================================================
// W [32768,1024] fp32 -> transposed bf16 hi/lo [1024][32768]
// =================================================================================
__global__ void __launch_bounds__(256) wconv_kernel(
    const float* __restrict__ W, __nv_bfloat16* __restrict__ Th, __nv_bfloat16* __restrict__ Tl)
{
    __shared__ float t[32][33];
    const int k0 = blockIdx.x * 32, n0 = blockIdx.y * 32;
    const int tx = threadIdx.x, ty = threadIdx.y;   // (32,8)
    #pragma unroll
    for (int r = 0; r < 4; r++)
        t[ty + 8*r][tx] = W[(size_t)(k0 + ty + 8*r)*1024 + n0 + tx];
    __syncthreads();
    #pragma unroll
    for (int r = 0; r < 4; r++) {
        const int nn = ty + 8*r;
        const float a = t[tx][nn];
        const __nv_bfloat16 h = __float2bfloat16_rn(a);
        const __nv_bfloat16 l = __float2bfloat16_rn(a - __bfloat162float(h));
        const size_t o = (size_t)(n0 + nn)*32768 + k0 + tx;
        Th[o] = h; Tl[o] = l;
    }
}

// =================================================================================
// fc1 GEMM via mma.sync (HMMA bf16, hi/lo split -> 3 products).
// A: [256,32768] bf16 hi/lo.  W: transposed [1024,32768] bf16 hi/lo (col-major B).
// CTA tile 128x128, 8 warps (warp tile 32x64), BK=32, split-K=16.
// grid = (8 Ntiles, 2 Mtiles, 16 Ksplits), 256 threads.
// smem row stride 40 bf16 (20 words) -> conflict-free STS + frag LDS.
// =================================================================================
#define MMA_BF16(d, a, bb)                                                                     \
    asm volatile("mma.sync.aligned.m16n8k16.row.col.f32.bf16.bf16.f32 "                        \
        "{%0,%1,%2,%3}, {%4,%5,%6,%7}, {%8,%9}, {%0,%1,%2,%3};"                                \
        : "+f"((d)[0]), "+f"((d)[1]), "+f"((d)[2]), "+f"((d)[3])                               \
        : "r"((a)[0]), "r"((a)[1]), "r"((a)[2]), "r"((a)[3]), "r"((bb)[0]), "r"((bb)[1]))

__global__ void __launch_bounds__(256) fc1_mma(
    const __nv_bfloat16* __restrict__ Ahi, const __nv_bfloat16* __restrict__ Alo,
    const __nv_bfloat16* __restrict__ Whi, const __nv_bfloat16* __restrict__ Wlo,
    float* __restrict__ P)
{
    constexpr int BK = 32, STRIDE = 40, KT = 32768;
    __shared__ __nv_bfloat16 sAh[128*STRIDE];
    __shared__ __nv_bfloat16 sAl[128*STRIDE];
    __shared__ __nv_bfloat16 sBh[128*STRIDE];
    __shared__ __nv_bfloat16 sBl[128*STRIDE];

    const int tid = threadIdx.x;
    const int wid = tid >> 5, lane = tid & 31;
    const int lr = lane >> 2, lc = lane & 3;
    const int wm = wid & 3;        // 4 warps along M (32 rows each)
    const int wn = wid >> 2;       // 2 warps along N (64 cols each)
    const int m0 = blockIdx.y * 128, n0 = blockIdx.x * 128;
    const int kbase = blockIdx.z * 2048;

    // global-load coords: 512 uint4 per 128x32 tile, 2 per thread
    const int r0g = tid >> 2,            c0g = (tid & 3) * 8;           // idx = tid
    const int r1g = (tid + 256) >> 2,    c1g = ((tid + 256) & 3) * 8;   // idx = tid+256

    const __nv_bfloat16* Ah0 = Ahi + (size_t)(m0 + r0g)*KT + kbase + c0g;
    const __nv_bfloat16* Ah1 = Ahi + (size_t)(m0 + r1g)*KT + kbase + c1g;
    const __nv_bfloat16* Al0 = Alo + (size_t)(m0 + r0g)*KT + kbase + c0g;
    const __nv_bfloat16* Al1 = Alo + (size_t)(m0 + r1g)*KT + kbase + c1g;
    const __nv_bfloat16* Bh0 = Whi + (size_t)(n0 + r0g)*KT + kbase + c0g;
    const __nv_bfloat16* Bh1 = Whi + (size_t)(n0 + r1g)*KT + kbase + c1g;
    const __nv_bfloat16* Bl0 = Wlo + (size_t)(n0 + r0g)*KT + kbase + c0g;
    const __nv_bfloat16* Bl1 = Wlo + (size_t)(n0 + r1g)*KT + kbase + c1g;

    float acc[2][8][4];
    #pragma unroll
    for (int mt = 0; mt < 2; mt++)
        #pragma unroll
        for (int nt = 0; nt < 8; nt++)
            #pragma unroll
            for (int e = 0; e < 4; e++) acc[mt][nt][e] = 0.f;

    uint4 pah0 = *(const uint4*)Ah0, pah1 = *(const uint4*)Ah1;
    uint4 pal0 = *(const uint4*)Al0, pal1 = *(const uint4*)Al1;
    uint4 pbh0 = *(const uint4*)Bh0, pbh1 = *(const uint4*)Bh1;
    uint4 pbl0 = *(const uint4*)Bl0, pbl1 = *(const uint4*)Bl1;

    for (int s = 0; s < 64; s++) {
        *(uint4*)&sAh[r0g*STRIDE + c0g] = pah0;  *(uint4*)&sAh[r1g*STRIDE + c1g] = pah1;
        *(uint4*)&sAl[r0g*STRIDE + c0g] = pal0;  *(uint4*)&sAl[r1g*STRIDE + c1g] = pal1;
        *(uint4*)&sBh[r0g*STRIDE + c0g] = pbh0;  *(uint4*)&sBh[r1g*STRIDE + c1g] = pbh1;
        *(uint4*)&sBl[r0g*STRIDE + c0g] = pbl0;  *(uint4*)&sBl[r1g*STRIDE + c1g] = pbl1;
        __syncthreads();
        if (s + 1 < 64) {
            const int off = (s + 1) * BK;
            pah0 = *(const uint4*)(Ah0 + off);  pah1 = *(const uint4*)(Ah1 + off);
            pal0 = *(const uint4*)(Al0 + off);  pal1 = *(const uint4*)(Al1 + off);
            pbh0 = *(const uint4*)(Bh0 + off);  pbh1 = *(const uint4*)(Bh1 + off);
            pbl0 = *(const uint4*)(Bl0 + off);  pbl1 = *(const uint4*)(Bl1 + off);
        }
        #pragma unroll
        for (int ks = 0; ks < 2; ks++) {
            const int kf = ks*16 + lc*2;
            uint32_t af[2][4], bf[8][2];
            // A hi fragments (rows wm*32 + mt*16 + lr)
            #pragma unroll
            for (int mt = 0; mt < 2; mt++) {
                const int r = wm*32 + mt*16 + lr;
                af[mt][0] = *(const uint32_t*)&sAh[ r     *STRIDE + kf];
                af[mt][1] = *(const uint32_t*)&sAh[(r + 8)*STRIDE + kf];
                af[mt][2] = *(const uint32_t*)&sAh[ r     *STRIDE + kf + 8];
                af[mt][3] = *(const uint32_t*)&sAh[(r + 8)*STRIDE + kf + 8];
            }
            // B hi fragments (cols wn*64 + nt*8 + lr)
            #pragma unroll
            for (int nt = 0; nt < 8; nt++) {
                const int nn = wn*64 + nt*8 + lr;
                bf[nt][0] = *(const uint32_t*)&sBh[nn*STRIDE + kf];
                bf[nt][1] = *(const uint32_t*)&sBh[nn*STRIDE + kf + 8];
            }
            #pragma unroll
            for (int mt = 0; mt < 2; mt++)
                #pragma unroll
                for (int nt = 0; nt < 8; nt++)
                    MMA_BF16(acc[mt][nt], af[mt], bf[nt]);   // hi*hi
            // A lo fragments -> lo*hi
            {
                uint32_t al[2][4];
                #pragma unroll
                for (int mt = 0; mt < 2; mt++) {
                    const int r = wm*32 + mt*16 + lr;
                    al[mt][0] = *(const uint32_t*)&sAl[ r     *STRIDE + kf];
                    al[mt][1] = *(const uint32_t*)&sAl[(r + 8)*STRIDE + kf];
                    al[mt][2] = *(const uint32_t*)&sAl[ r     *STRIDE + kf + 8];
                    al[mt][3] = *(const uint32_t*)&sAl[(r + 8)*STRIDE + kf + 8];
                }
                #pragma unroll
                for (int mt = 0; mt < 2; mt++)
                    #pragma unroll
                    for (int nt = 0; nt < 8; nt++)
                        MMA_BF16(acc[mt][nt], al[mt], bf[nt]);
            }
            // B lo fragments (reuse bf regs) -> hi*lo
            #pragma unroll
            for (int nt = 0; nt < 8; nt++) {
                const int nn = wn*64 + nt*8 + lr;
                bf[nt][0] = *(const uint32_t*)&sBl[nn*STRIDE + kf];
                bf[nt][1] = *(const uint32_t*)&sBl[nn*STRIDE + kf + 8];
            }
            #pragma unroll
            for (int mt = 0; mt < 2; mt++)
                #pragma unroll
                for (int nt = 0; nt < 8; nt++)
                    MMA_BF16(acc[mt][nt], af[mt], bf[nt]);
        }
        __syncthreads();
    }

    float* Pp = P + (size_t)blockIdx.z * 262144;
    #pragma unroll
    for (int mt = 0; mt < 2; mt++) {
        const int r = m0 + wm*32 + mt*16 + lr;
        #pragma unroll
        for (int nt = 0; nt < 8; nt++) {
            const int cc = n0 + wn*64 + nt*8 + lc*2;
            *(float2*)(Pp + (size_t)r*1024 + cc)       = make_float2(acc[mt][nt][0], acc[mt][nt][1]);
            *(float2*)(Pp + (size_t)(r + 8)*1024 + cc) = make_float2(acc[mt][nt][2], acc[mt][nt][3]);
        }
    }
}

// fc1 partial reduction + bias + relu
__global__ void fc1_reduce(const float* __restrict__ P, const float* __restrict__ Bb,
                           float* __restrict__ O)
{
    const int idx = blockIdx.x * blockDim.x + threadIdx.x;   // 262144 total
    float s = Bb[idx & 1023];
    #pragma unroll
    for (int sp = 0; sp < 16; sp++) s += P[sp*262144 + idx];
    O[idx] = fmaxf(s, 0.f);
}

// fc2: [256,1024] @ [1024,10] + b
__global__ void fc2_kernel(const float* __restrict__ H, const float* __restrict__ W,
                           const float* __restrict__ Bb, float* __restrict__ out)
{
    const int b = blockIdx.x, tid = threadIdx.x;
    float acc[10];
    #pragma unroll
    for (int o = 0; o < 10; o++) acc[o] = 0.f;
    for (int k = tid; k < 1024; k += 128) {
        const float hv = H[b*1024 + k];
        const float* wr = W + k*10;
        #pragma unroll
        for (int o = 0; o < 10; o++) acc[o] += hv * wr[o];
    }
    __shared__ float red[4][10];
    #pragma unroll
    for (int o = 0; o < 10; o++) {
        #pragma unroll
        for (int off = 16; off; off >>= 1)
            acc[o] += __shfl_down_sync(0xffffffffu, acc[o], off);
    }
    if ((tid & 31) == 0) {
        #pragma unroll
        for (int o = 0; o < 10; o++) red[tid >> 5][o] = acc[o];
    }
    __syncthreads();
    if (tid < 10)
        out[b*10 + tid] = Bb[tid] + red[0][tid] + red[1][tid] + red[2][tid] + red[3][tid];
}

// =================================================================================
extern "C" void kernel_launch(void* const* d_in, const int* in_sizes, int n_in,
                              void* d_out, int out_size)
{
    const float* x    = (const float*)d_in[0];
    const float* w1c  = (const float*)d_in[1];
    const float* b1c  = (const float*)d_in[2];
    const float* w1q  = (const float*)d_in[3];
    const float* w1k  = (const float*)d_in[4];
    const float* w1v  = (const float*)d_in[5];
    const float* w1o  = (const float*)d_in[6];
    const float* b1o  = (const float*)d_in[7];
    const float* w2c  = (const float*)d_in[8];
    const float* b2c  = (const float*)d_in[9];
    const float* w2q  = (const float*)d_in[10];
    const float* w2k  = (const float*)d_in[11];
    const float* w2v  = (const float*)d_in[12];
    const float* w2o  = (const float*)d_in[13];
    const float* b2o  = (const float*)d_in[14];
    const float* fc1w = (const float*)d_in[15];
    const float* fc1b = (const float*)d_in[16];
    const float* fc2w = (const float*)d_in[17];
    const float* fc2b = (const float*)d_in[18];
    float* out = (float*)d_out;

    float *h1, *part, *fch;
    __nv_bfloat16 *ahi, *alo, *whi, *wlo;
    cudaGetSymbolAddress((void**)&h1,   g_h1);
    cudaGetSymbolAddress((void**)&ahi,  g_Ahi);
    cudaGetSymbolAddress((void**)&alo,  g_Alo);
    cudaGetSymbolAddress((void**)&whi,  g_Whi);
    cudaGetSymbolAddress((void**)&wlo,  g_Wlo);
    cudaGetSymbolAddress((void**)&part, g_part);
    cudaGetSymbolAddress((void**)&fch,  g_fc1);

    const int SM1 = (12*16 + 3*12*16 + (16+16)*64 + 16 + 64  + 2*256*(16+4)) * 4;
    const int SM2 = (64*32 + 3*64*32 + (32+32)*128 + 32 + 128 + 2*256*(32+4)) * 4;

    cudaFuncSetAttribute(attn_kernel<3,12,16,16,64>,
                         cudaFuncAttributeMaxDynamicSharedMemorySize, SM1);
    cudaFuncSetAttribute(attn_kernel<16,64,32,32,128>,
                         cudaFuncAttributeMaxDynamicSharedMemorySize, SM2);

    wconv_kernel<<<dim3(1024, 32), dim3(32, 8)>>>(fc1w, whi, wlo);
    attn_kernel<3,12,16,16,64><<<256, 256, SM1>>>(x,  w1c, b1c, w1q, w1k, w1v, w1o, b1o,
                                                  h1, nullptr, nullptr);
    attn_kernel<16,64,32,32,128><<<256, 256, SM2>>>(h1, w2c, b2c, w2q, w2k, w2v, w2o, b2o,
                                                  nullptr, ahi, alo);
    fc1_mma<<<dim3(8, 2, 16), 256>>>(ahi, alo, whi, wlo, part);
    fc1_reduce<<<1024, 256>>>(part, fc1b, fch);
    fc2_kernel<<<256, 128>>>(fch, fc2w, fc2b, out);
}

// round 8
// speedup vs baseline: 1.5160x; 1.1609x over previous
#include <cuda_runtime.h>
#include <cuda_bf16.h>
#include <cuda_fp16.h>
#include <cstdint>
#include <stdint.h>
#include <math.h>

// ---------------- scratch (device globals; no allocation allowed) ----------------
__device__ float g_h1[256*16*32*32];        // layer1 output [B,16,32,32]
__device__ __half g_Ahi[256*32768];         // fc input, fp16 hi
__device__ __half g_Alo[256*32768];         // fc input, fp16 lo residual
__device__ __half g_Wh[1024ull*32768];      // fc1 weight TRANSPOSED [N,K], fp16
__device__ float g_part[9*256*1024];        // fc1 split-K partials
__device__ float g_fc1[256*1024];           // fc1 output (post relu)

__device__ __forceinline__ uint32_t smem_u32(const void* p) {
    uint32_t a;
    asm("{ .reg .u64 t; cvta.to.shared.u64 t, %1; cvt.u32.u64 %0, t; }" : "=r"(a) : "l"(p));
    return a;
}
__device__ __forceinline__ void ldsm4(uint32_t* r, uint32_t addr) {
    asm volatile("ldmatrix.sync.aligned.m8n8.x4.shared.b16 {%0,%1,%2,%3}, [%4];"
                 : "=r"(r[0]), "=r"(r[1]), "=r"(r[2]), "=r"(r[3]) : "r"(addr));
}
#define MMA_F16(d, a, bb)                                                                      \
    asm volatile("mma.sync.aligned.m16n8k16.row.col.f32.f16.f16.f32 "                          \
        "{%0,%1,%2,%3}, {%4,%5,%6,%7}, {%8,%9}, {%0,%1,%2,%3};"                                \
        : "+f"((d)[0]), "+f"((d)[1]), "+f"((d)[2]), "+f"((d)[3])                               \
        : "r"((a)[0]), "r"((a)[1]), "r"((a)[2]), "r"((a)[3]), "r"((bb)[0]), "r"((bb)[1]))

// =================================================================================
// Fused ConvNN-branch attention layer. grid = B, block = 256 (one thread/token).
// If Ahi/Alo non-null (layer 2), emits fp16 hi/lo split of output instead of fp32.
// =================================================================================
template<int CIN, int CU, int R, int D, int CO>
__global__ void __launch_bounds__(256, 1) attn_kernel(
    const float* __restrict__ X,
    const float* __restrict__ Wc, const float* __restrict__ Bc,
    const float* __restrict__ Wq, const float* __restrict__ Wk, const float* __restrict__ Wv,
    const float* __restrict__ Wo, const float* __restrict__ Bo,
    float* __restrict__ Y, __half* __restrict__ Ahi, __half* __restrict__ Alo)
{
    constexpr int NTOK = 256;
    constexpr int NHEADS = 4;
    constexpr int DH = D / NHEADS;
    constexpr int KNN = 9;
    constexpr int DPAD = D + 4;
    constexpr int COUT = CO / 4;

    extern __shared__ float smem[];
    float* sWc = smem;
    float* sWq = sWc + CU*R;
    float* sWk = sWq + CU*D;
    float* sWv = sWk + CU*D;
    float* sWo = sWv + CU*D;
    float* sBc = sWo + (R+D)*CO;
    float* sBo = sBc + R;
    float* sK  = sBo + CO;
    float* sV  = sK + NTOK*DPAD;

    const int b = blockIdx.x;
    const int n = threadIdx.x;

    for (int idx = n; idx < CU*R; idx += NTOK) sWc[idx] = Wc[idx];
    for (int idx = n; idx < CU*D; idx += NTOK) { sWq[idx]=Wq[idx]; sWk[idx]=Wk[idx]; sWv[idx]=Wv[idx]; }
    for (int idx = n; idx < (R+D)*CO; idx += NTOK) sWo[idx] = Wo[idx];
    if (n < R)  sBc[n] = Bc[n];
    if (n < CO) sBo[n] = Bo[n];
    __syncthreads();

    const int i = n >> 4;
    const int j = n & 15;

    float q[D], ka[D], va[D], loc[R];
    #pragma unroll
    for (int dd = 0; dd < D; dd++) { q[dd]=0.f; ka[dd]=0.f; va[dd]=0.f; }
    #pragma unroll
    for (int rr = 0; rr < R; rr++) loc[rr] = sBc[rr];

    #pragma unroll 4
    for (int c = 0; c < CU; c++) {
        const int ch = c >> 2, si = (c >> 1) & 1, sj = c & 1;
        const float tv = X[((b*CIN + ch)*32 + 2*i + si)*32 + 2*j + sj];
        const float4* wq4 = reinterpret_cast<const float4*>(sWq + c*D);
        const float4* wk4 = reinterpret_cast<const float4*>(sWk + c*D);
        const float4* wv4 = reinterpret_cast<const float4*>(sWv + c*D);
        const float4* wc4 = reinterpret_cast<const float4*>(sWc + c*R);
        #pragma unroll
        for (int d4 = 0; d4 < D/4; d4++) {
            float4 w;
            w = wq4[d4]; q[4*d4]+=tv*w.x;  q[4*d4+1]+=tv*w.y;  q[4*d4+2]+=tv*w.z;  q[4*d4+3]+=tv*w.w;
            w = wk4[d4]; ka[4*d4]+=tv*w.x; ka[4*d4+1]+=tv*w.y; ka[4*d4+2]+=tv*w.z; ka[4*d4+3]+=tv*w.w;
            w = wv4[d4]; va[4*d4]+=tv*w.x; va[4*d4+1]+=tv*w.y; va[4*d4+2]+=tv*w.z; va[4*d4+3]+=tv*w.w;
        }
        #pragma unroll
        for (int r4 = 0; r4 < R/4; r4++) {
            float4 w = wc4[r4];
            loc[4*r4]+=tv*w.x; loc[4*r4+1]+=tv*w.y; loc[4*r4+2]+=tv*w.z; loc[4*r4+3]+=tv*w.w;
        }
    }
    #pragma unroll
    for (int rr = 0; rr < R; rr++) loc[rr] = fmaxf(loc[rr], 0.f);
    #pragma unroll
    for (int d4 = 0; d4 < D/4; d4++) {
        reinterpret_cast<float4*>(sK + n*DPAD)[d4] = make_float4(ka[4*d4],ka[4*d4+1],ka[4*d4+2],ka[4*d4+3]);
        reinterpret_cast<float4*>(sV + n*DPAD)[d4] = make_float4(va[4*d4],va[4*d4+1],va[4*d4+2],va[4*d4+3]);
    }
    __syncthreads();

    float topv[KNN]; int topi[KNN];
    #pragma unroll
    for (int kk = 0; kk < KNN; kk++) { topv[kk] = -1e30f; topi[kk] = 0; }

    for (int m = 0; m < NTOK; m++) {
        const float4* kp = reinterpret_cast<const float4*>(sK + m*DPAD);
        float dot = 0.f;
        #pragma unroll
        for (int d4 = 0; d4 < D/4; d4++) {
            float4 kv = kp[d4];
            dot += q[4*d4]*kv.x + q[4*d4+1]*kv.y + q[4*d4+2]*kv.z + q[4*d4+3]*kv.w;
        }
        if (dot > topv[KNN-1]) {
            topv[KNN-1] = dot; topi[KNN-1] = m;
            #pragma unroll
            for (int jj = KNN-1; jj > 0; --jj) {
                if (topv[jj] > topv[jj-1]) {
                    float tv_ = topv[jj]; topv[jj] = topv[jj-1]; topv[jj-1] = tv_;
                    int   ti_ = topi[jj]; topi[jj] = topi[jj-1]; topi[jj-1] = ti_;
                }
            }
        }
    }

    const float scale = 1.0f / sqrtf((float)DH);
    float agg[D];
    #pragma unroll
    for (int h = 0; h < NHEADS; h++) {
        float lg[KNN];
        #pragma unroll
        for (int kk = 0; kk < KNN; kk++) {
            const float4* kr = reinterpret_cast<const float4*>(sK + topi[kk]*DPAD + h*DH);
            float s = 0.f;
            #pragma unroll
            for (int d4 = 0; d4 < DH/4; d4++) {
                float4 kv = kr[d4];
                s += q[h*DH+4*d4]*kv.x + q[h*DH+4*d4+1]*kv.y + q[h*DH+4*d4+2]*kv.z + q[h*DH+4*d4+3]*kv.w;
            }
            lg[kk] = s * scale;
        }
        float mx = lg[0];
        #pragma unroll
        for (int kk = 1; kk < KNN; kk++) mx = fmaxf(mx, lg[kk]);
        float den = 0.f;
        #pragma unroll
        for (int kk = 0; kk < KNN; kk++) { lg[kk] = expf(lg[kk] - mx); den += lg[kk]; }
        const float inv = 1.0f / den;

        float ah[DH];
        #pragma unroll
        for (int dd = 0; dd < DH; dd++) ah[dd] = 0.f;
        #pragma unroll
        for (int kk = 0; kk < KNN; kk++) {
            const float w = lg[kk];
            const float4* vr = reinterpret_cast<const float4*>(sV + topi[kk]*DPAD + h*DH);
            #pragma unroll
            for (int d4 = 0; d4 < DH/4; d4++) {
                float4 vv = vr[d4];
                ah[4*d4]+=w*vv.x; ah[4*d4+1]+=w*vv.y; ah[4*d4+2]+=w*vv.z; ah[4*d4+3]+=w*vv.w;
            }
        }
        #pragma unroll
        for (int dd = 0; dd < DH; dd++) agg[h*DH+dd] = ah[dd]*inv;
    }

    #pragma unroll 1
    for (int cog = 0; cog < COUT; cog++) {
        float o0 = sBo[4*cog+0], o1 = sBo[4*cog+1], o2 = sBo[4*cog+2], o3 = sBo[4*cog+3];
        #pragma unroll
        for (int rr = 0; rr < R; rr++) {
            const float lv = loc[rr];
            const float4 w = reinterpret_cast<const float4*>(sWo + rr*CO)[cog];
            o0 += lv*w.x; o1 += lv*w.y; o2 += lv*w.z; o3 += lv*w.w;
        }
        #pragma unroll
        for (int dd = 0; dd < D; dd++) {
            const float av = agg[dd];
            const float4 w = reinterpret_cast<const float4*>(sWo + (R+dd)*CO)[cog];
            o0 += av*w.x; o1 += av*w.y; o2 += av*w.z; o3 += av*w.w;
        }
        if (Ahi) {
            // flat fc-input index: f = cog*1024 + (2i+si)*32 + (2j+sj)
            const size_t base = (size_t)b*32768 + (size_t)cog*1024 + (size_t)(2*i)*32 + 2*j;
            __half h0=__float2half_rn(o0), h1=__float2half_rn(o1);
            __half h2=__float2half_rn(o2), h3=__float2half_rn(o3);
            __half l0=__float2half_rn(o0-__half2float(h0));
            __half l1=__float2half_rn(o1-__half2float(h1));
            __half l2=__float2half_rn(o2-__half2float(h2));
            __half l3=__float2half_rn(o3-__half2float(h3));
            __half2 ph; ph.x=h0; ph.y=h1;
            __half2 pl; pl.x=l0; pl.y=l1;
            *reinterpret_cast<__half2*>(Ahi + base) = ph;
            *reinterpret_cast<__half2*>(Alo + base) = pl;
            ph.x=h2; ph.y=h3; pl.x=l2; pl.y=l3;
            *reinterpret_cast<__half2*>(Ahi + base + 32) = ph;
            *reinterpret_cast<__half2*>(Alo + base + 32) = pl;
        } else {
            float* yb = Y + ((size_t)(b*COUT + cog)*32 + 2*i)*32 + 2*j;
            *reinterpret_cast<float2*>(yb)      = make_float2(o0, o1);
            *reinterpret_cast<float2*>(yb + 32) = make_float2(o2, o3);
        }
    }
}

// =================================================================================
// W [32768,1024] fp32 -> transposed fp16 [1024][32768]
// =================================================================================
__global__ void __launch_bounds__(256) wconv_kernel(
    const float* __restrict__ W, __half* __restrict__ Th)
{
    __shared__ float t[32][33];
    const int k0 = blockIdx.x * 32, n0 = blockIdx.y * 32;
    const int tx = threadIdx.x, ty = threadIdx.y;   // (32,8)
    #pragma unroll
    for (int r = 0; r < 4; r++)
        t[ty + 8*r][tx] = W[(size_t)(k0 + ty + 8*r)*1024 + n0 + tx];
    __syncthreads();
    #pragma unroll
    for (int r = 0; r < 4; r++) {
        const int nn = ty + 8*r;
        Th[(size_t)(n0 + nn)*32768 + k0 + tx] = __float2half_rn(t[tx][nn]);
    }
}

// =================================================================================
// fc1 GEMM via mma.sync fp16 (A hi/lo split -> 2 products; W single fp16).
// CTA tile 128x128, 8 warps (warp 32x64), BK=32, double-buffered smem, ldmatrix.
// grid = (8 Ntiles, 2 Mtiles, 9 Ksplits) = 144 CTAs (~one wave).
// smem row stride 40 halves (80B): ldmatrix conflict-free.
// =================================================================================
__global__ void __launch_bounds__(256) fc1_mma(
    const __half* __restrict__ Ahi, const __half* __restrict__ Alo,
    const __half* __restrict__ Wh, float* __restrict__ P)
{
    extern __shared__ char sm[];
    constexpr int KT = 32768;
    constexpr uint32_t OAL = 10240, OWH = 20480, BUFS = 30720;  // tile=128*40*2=10240B

    const int tid = threadIdx.x, wid = tid >> 5, lane = tid & 31;
    const int lr = lane >> 2, lc = lane & 3;
    const int tr = lane & 7, tq = lane >> 3;
    const int wm = wid & 3, wn = wid >> 2;
    const int m0 = blockIdx.y * 128, n0 = blockIdx.x * 128;
    const int ksp = blockIdx.z;
    const int sbase = ksp * 114;                   // stage = 32 K-elems; 1024 stages total
    const int nstage = (ksp < 8) ? 114 : 112;

    const uint32_t smb = smem_u32(sm);
    const uint32_t rowA = (uint32_t)((tr + (tq & 1)*8)*80 + (tq >> 1)*16);
    const uint32_t rowB = (uint32_t)((tr + (tq >> 1)*8)*80 + (tq & 1)*16);

    const int r0g = tid >> 2, c0g = (tid & 3)*8;
    const __half* gAh = Ahi + (size_t)(m0 + r0g)*KT + c0g;
    const __half* gAl = Alo + (size_t)(m0 + r0g)*KT + c0g;
    const __half* gW  = Wh  + (size_t)(n0 + r0g)*KT + c0g;
    const size_t row64 = (size_t)64*KT;
    const uint32_t soff = (uint32_t)(r0g*80 + c0g*2);

    float acc[2][8][4];
    #pragma unroll
    for (int mt = 0; mt < 2; mt++)
        #pragma unroll
        for (int nt = 0; nt < 8; nt++)
            #pragma unroll
            for (int e = 0; e < 4; e++) acc[mt][nt][e] = 0.f;

    uint4 pa0, pa1, pl0, pl1, pw0, pw1;
    {
        const int kk = sbase*32;
        pa0 = *(const uint4*)(gAh + kk); pa1 = *(const uint4*)(gAh + row64 + kk);
        pl0 = *(const uint4*)(gAl + kk); pl1 = *(const uint4*)(gAl + row64 + kk);
        pw0 = *(const uint4*)(gW  + kk); pw1 = *(const uint4*)(gW  + row64 + kk);
        char* b = sm + soff;
        *(uint4*)(b)                = pa0; *(uint4*)(b + 64*80)       = pa1;
        *(uint4*)(b + OAL)          = pl0; *(uint4*)(b + OAL + 64*80) = pl1;
        *(uint4*)(b + OWH)          = pw0; *(uint4*)(b + OWH + 64*80) = pw1;
    }
    __syncthreads();

    for (int s = 0; s < nstage; s++) {
        if (s + 1 < nstage) {
            const int kk = (sbase + s + 1)*32;
            pa0 = *(const uint4*)(gAh + kk); pa1 = *(const uint4*)(gAh + row64 + kk);
            pl0 = *(const uint4*)(gAl + kk); pl1 = *(const uint4*)(gAl + row64 + kk);
            pw0 = *(const uint4*)(gW  + kk); pw1 = *(const uint4*)(gW  + row64 + kk);
        }
        const uint32_t base = smb + (uint32_t)(s & 1)*BUFS;
        const uint32_t aH = base + (uint32_t)(wm*32)*80 + rowA;
        const uint32_t aL = aH + OAL;
        const uint32_t bB = base + OWH + (uint32_t)(wn*64)*80 + rowB;
        #pragma unroll
        for (int ks = 0; ks < 2; ks++) {
            const uint32_t kb = ks*32;
            uint32_t afh[2][4], afl[2][4], bfr[4][4];
            ldsm4(afh[0], aH + kb);            ldsm4(afh[1], aH + 16*80 + kb);
            ldsm4(afl[0], aL + kb);            ldsm4(afl[1], aL + 16*80 + kb);
            #pragma unroll
            for (int p = 0; p < 4; p++) ldsm4(bfr[p], bB + (uint32_t)(p*16)*80 + kb);
            #pragma unroll
            for (int mt = 0; mt < 2; mt++)
                #pragma unroll
                for (int nt = 0; nt < 8; nt++) {
                    uint32_t* bb = &bfr[nt >> 1][(nt & 1)*2];
                    MMA_F16(acc[mt][nt], afh[mt], bb);
                    MMA_F16(acc[mt][nt], afl[mt], bb);
                }
        }
        if (s + 1 < nstage) {
            char* b = sm + ((s + 1) & 1)*BUFS + soff;
            *(uint4*)(b)                = pa0; *(uint4*)(b + 64*80)       = pa1;
            *(uint4*)(b + OAL)          = pl0; *(uint4*)(b + OAL + 64*80) = pl1;
            *(uint4*)(b + OWH)          = pw0; *(uint4*)(b + OWH + 64*80) = pw1;
            __syncthreads();
        }
    }

    float* Pp = P + (size_t)ksp * 262144;
    #pragma unroll
    for (int mt = 0; mt < 2; mt++) {
        const int r = m0 + wm*32 + mt*16 + lr;
        #pragma unroll
        for (int nt = 0; nt < 8; nt++) {
            const int cc = n0 + wn*64 + nt*8 + lc*2;
            *(float2*)(Pp + (size_t)r*1024 + cc)       = make_float2(acc[mt][nt][0], acc[mt][nt][1]);
            *(float2*)(Pp + (size_t)(r + 8)*1024 + cc) = make_float2(acc[mt][nt][2], acc[mt][nt][3]);
        }
    }
}

// fc1 partial reduction + bias + relu
__global__ void fc1_reduce(const float* __restrict__ P, const float* __restrict__ Bb,
                           float* __restrict__ O)
{
    const int idx = blockIdx.x * blockDim.x + threadIdx.x;   // 262144 total
    float s = Bb[idx & 1023];
    #pragma unroll
    for (int sp = 0; sp < 9; sp++) s += P[sp*262144 + idx];
    O[idx] = fmaxf(s, 0.f);
}

// fc2: [256,1024] @ [1024,10] + b
__global__ void fc2_kernel(const float* __restrict__ H, const float* __restrict__ W,
                           const float* __restrict__ Bb, float* __restrict__ out)
{
    const int b = blockIdx.x, tid = threadIdx.x;
    float acc[10];
    #pragma unroll
    for (int o = 0; o < 10; o++) acc[o] = 0.f;
    for (int k = tid; k < 1024; k += 128) {
        const float hv = H[b*1024 + k];
        const float* wr = W + k*10;
        #pragma unroll
        for (int o = 0; o < 10; o++) acc[o] += hv * wr[o];
    }
    __shared__ float red[4][10];
    #pragma unroll
    for (int o = 0; o < 10; o++) {
        #pragma unroll
        for (int off = 16; off; off >>= 1)
            acc[o] += __shfl_down_sync(0xffffffffu, acc[o], off);
    }
    if ((tid & 31) == 0) {
        #pragma unroll
        for (int o = 0; o < 10; o++) red[tid >> 5][o] = acc[o];
    }
    __syncthreads();
    if (tid < 10)
        out[b*10 + tid] = Bb[tid] + red[0][tid] + red[1][tid] + red[2][tid] + red[3][tid];
}

// =================================================================================
extern "C" void kernel_launch(void* const* d_in, const int* in_sizes, int n_in,
                              void* d_out, int out_size)
{
    const float* x    = (const float*)d_in[0];
    const float* w1c  = (const float*)d_in[1];
    const float* b1c  = (const float*)d_in[2];
    const float* w1q  = (const float*)d_in[3];
    const float* w1k  = (const float*)d_in[4];
    const float* w1v  = (const float*)d_in[5];
    const float* w1o  = (const float*)d_in[6];
    const float* b1o  = (const float*)d_in[7];
    const float* w2c  = (const float*)d_in[8];
    const float* b2c  = (const float*)d_in[9];
    const float* w2q  = (const float*)d_in[10];
    const float* w2k  = (const float*)d_in[11];
    const float* w2v  = (const float*)d_in[12];
    const float* w2o  = (const float*)d_in[13];
    const float* b2o  = (const float*)d_in[14];
    const float* fc1w = (const float*)d_in[15];
    const float* fc1b = (const float*)d_in[16];
    const float* fc2w = (const float*)d_in[17];
    const float* fc2b = (const float*)d_in[18];
    float* out = (float*)d_out;

    float *h1, *part, *fch;
    __half *ahi, *alo, *wh;
    cudaGetSymbolAddress((void**)&h1,   g_h1);
    cudaGetSymbolAddress((void**)&ahi,  g_Ahi);
    cudaGetSymbolAddress((void**)&alo,  g_Alo);
    cudaGetSymbolAddress((void**)&wh,   g_Wh);
    cudaGetSymbolAddress((void**)&part, g_part);
    cudaGetSymbolAddress((void**)&fch,  g_fc1);

    const int SM1 = (12*16 + 3*12*16 + (16+16)*64 + 16 + 64  + 2*256*(16+4)) * 4;
    const int SM2 = (64*32 + 3*64*32 + (32+32)*128 + 32 + 128 + 2*256*(32+4)) * 4;
    const int SMG = 61440;   // 2 buffers x 3 tiles x 10240B

    cudaFuncSetAttribute(attn_kernel<3,12,16,16,64>,
                         cudaFuncAttributeMaxDynamicSharedMemorySize, SM1);
    cudaFuncSetAttribute(attn_kernel<16,64,32,32,128>,
                         cudaFuncAttributeMaxDynamicSharedMemorySize, SM2);
    cudaFuncSetAttribute(fc1_mma,
                         cudaFuncAttributeMaxDynamicSharedMemorySize, SMG);

    wconv_kernel<<<dim3(1024, 32), dim3(32, 8)>>>(fc1w, wh);
    attn_kernel<3,12,16,16,64><<<256, 256, SM1>>>(x,  w1c, b1c, w1q, w1k, w1v, w1o, b1o,
                                                  h1, nullptr, nullptr);
    attn_kernel<16,64,32,32,128><<<256, 256, SM2>>>(h1, w2c, b2c, w2q, w2k, w2v, w2o, b2o,
                                                  nullptr, ahi, alo);
    fc1_mma<<<dim3(8, 2, 9), 256, SMG>>>(ahi, alo, wh, part);
    fc1_reduce<<<1024, 256>>>(part, fc1b, fch);
    fc2_kernel<<<256, 128>>>(fch, fc2w, fc2b, out);
}

// round 9
// speedup vs baseline: 1.5656x; 1.0328x over previous
#include <cuda_runtime.h>
#include <cuda_bf16.h>
#include <cuda_fp16.h>
#include <cstdint>
#include <stdint.h>
#include <math.h>

// ---------------- scratch (device globals; no allocation allowed) ----------------
__device__ float g_h1[256*16*32*32];        // layer1 output [B,16,32,32]
__device__ __half g_Ahi[256*32768];         // fc input, fp16 hi
__device__ __half g_Alo[256*32768];         // fc input, fp16 lo residual
__device__ __half g_Wh[1024ull*32768];      // fc1 weight TRANSPOSED [N,K], fp16
__device__ float g_part[9*256*1024];        // fc1 split-K partials
__device__ float g_fc1[256*1024];           // fc1 output (post relu)

__device__ __forceinline__ uint32_t smem_u32(const void* p) {
    uint32_t a;
    asm("{ .reg .u64 t; cvta.to.shared.u64 t, %1; cvt.u32.u64 %0, t; }" : "=r"(a) : "l"(p));
    return a;
}
__device__ __forceinline__ void ldsm4(uint32_t* r, uint32_t addr) {
    asm volatile("ldmatrix.sync.aligned.m8n8.x4.shared.b16 {%0,%1,%2,%3}, [%4];"
                 : "=r"(r[0]), "=r"(r[1]), "=r"(r[2]), "=r"(r[3]) : "r"(addr));
}
__device__ __forceinline__ void cpa16(uint32_t dst, const void* src) {
    asm volatile("cp.async.ca.shared.global [%0], [%1], 16;" :: "r"(dst), "l"(src));
}
#define CP_COMMIT() asm volatile("cp.async.commit_group;" ::: "memory")
#define CP_WAIT2()  asm volatile("cp.async.wait_group 2;" ::: "memory")
#define MMA_F16(d, a, bb)                                                                      \
    asm volatile("mma.sync.aligned.m16n8k16.row.col.f32.f16.f16.f32 "                          \
        "{%0,%1,%2,%3}, {%4,%5,%6,%7}, {%8,%9}, {%0,%1,%2,%3};"                                \
        : "+f"((d)[0]), "+f"((d)[1]), "+f"((d)[2]), "+f"((d)[3])                               \
        : "r"((a)[0]), "r"((a)[1]), "r"((a)[2]), "r"((a)[3]), "r"((bb)[0]), "r"((bb)[1]))

// =================================================================================
// Fused ConvNN-branch attention layer. grid = B, block = 256 (one thread/token).
// If Ahi/Alo non-null (layer 2), emits fp16 hi/lo split of output instead of fp32.
// =================================================================================
template<int CIN, int CU, int R, int D, int CO>
__global__ void __launch_bounds__(256, 1) attn_kernel(
    const float* __restrict__ X,
    const float* __restrict__ Wc, const float* __restrict__ Bc,
    const float* __restrict__ Wq, const float* __restrict__ Wk, const float* __restrict__ Wv,
    const float* __restrict__ Wo, const float* __restrict__ Bo,
    float* __restrict__ Y, __half* __restrict__ Ahi, __half* __restrict__ Alo)
{
    constexpr int NTOK = 256;
    constexpr int NHEADS = 4;
    constexpr int DH = D / NHEADS;
    constexpr int KNN = 9;
    constexpr int DPAD = D + 4;
    constexpr int COUT = CO / 4;

    extern __shared__ float smem[];
    float* sWc = smem;
    float* sWq = sWc + CU*R;
    float* sWk = sWq + CU*D;
    float* sWv = sWk + CU*D;
    float* sWo = sWv + CU*D;
    float* sBc = sWo + (R+D)*CO;
    float* sBo = sBc + R;
    float* sK  = sBo + CO;
    float* sV  = sK + NTOK*DPAD;

    const int b = blockIdx.x;
    const int n = threadIdx.x;

    for (int idx = n; idx < CU*R; idx += NTOK) sWc[idx] = Wc[idx];
    for (int idx = n; idx < CU*D; idx += NTOK) { sWq[idx]=Wq[idx]; sWk[idx]=Wk[idx]; sWv[idx]=Wv[idx]; }
    for (int idx = n; idx < (R+D)*CO; idx += NTOK) sWo[idx] = Wo[idx];
    if (n < R)  sBc[n] = Bc[n];
    if (n < CO) sBo[n] = Bo[n];
    __syncthreads();

    const int i = n >> 4;
    const int j = n & 15;

    float q[D], ka[D], va[D], loc[R];
    #pragma unroll
    for (int dd = 0; dd < D; dd++) { q[dd]=0.f; ka[dd]=0.f; va[dd]=0.f; }
    #pragma unroll
    for (int rr = 0; rr < R; rr++) loc[rr] = sBc[rr];

    #pragma unroll 4
    for (int c = 0; c < CU; c++) {
        const int ch = c >> 2, si = (c >> 1) & 1, sj = c & 1;
        const float tv = X[((b*CIN + ch)*32 + 2*i + si)*32 + 2*j + sj];
        const float4* wq4 = reinterpret_cast<const float4*>(sWq + c*D);
        const float4* wk4 = reinterpret_cast<const float4*>(sWk + c*D);
        const float4* wv4 = reinterpret_cast<const float4*>(sWv + c*D);
        const float4* wc4 = reinterpret_cast<const float4*>(sWc + c*R);
        #pragma unroll
        for (int d4 = 0; d4 < D/4; d4++) {
            float4 w;
            w = wq4[d4]; q[4*d4]+=tv*w.x;  q[4*d4+1]+=tv*w.y;  q[4*d4+2]+=tv*w.z;  q[4*d4+3]+=tv*w.w;
            w = wk4[d4]; ka[4*d4]+=tv*w.x; ka[4*d4+1]+=tv*w.y; ka[4*d4+2]+=tv*w.z; ka[4*d4+3]+=tv*w.w;
            w = wv4[d4]; va[4*d4]+=tv*w.x; va[4*d4+1]+=tv*w.y; va[4*d4+2]+=tv*w.z; va[4*d4+3]+=tv*w.w;
        }
        #pragma unroll
        for (int r4 = 0; r4 < R/4; r4++) {
            float4 w = wc4[r4];
            loc[4*r4]+=tv*w.x; loc[4*r4+1]+=tv*w.y; loc[4*r4+2]+=tv*w.z; loc[4*r4+3]+=tv*w.w;
        }
    }
    #pragma unroll
    for (int rr = 0; rr < R; rr++) loc[rr] = fmaxf(loc[rr], 0.f);
    #pragma unroll
    for (int d4 = 0; d4 < D/4; d4++) {
        reinterpret_cast<float4*>(sK + n*DPAD)[d4] = make_float4(ka[4*d4],ka[4*d4+1],ka[4*d4+2],ka[4*d4+3]);
        reinterpret_cast<float4*>(sV + n*DPAD)[d4] = make_float4(va[4*d4],va[4*d4+1],va[4*d4+2],va[4*d4+3]);
    }
    __syncthreads();

    float topv[KNN]; int topi[KNN];
    #pragma unroll
    for (int kk = 0; kk < KNN; kk++) { topv[kk] = -1e30f; topi[kk] = 0; }

    for (int m = 0; m < NTOK; m++) {
        const float4* kp = reinterpret_cast<const float4*>(sK + m*DPAD);
        float dot = 0.f;
        #pragma unroll
        for (int d4 = 0; d4 < D/4; d4++) {
            float4 kv = kp[d4];
            dot += q[4*d4]*kv.x + q[4*d4+1]*kv.y + q[4*d4+2]*kv.z + q[4*d4+3]*kv.w;
        }
        if (dot > topv[KNN-1]) {
            topv[KNN-1] = dot; topi[KNN-1] = m;
            #pragma unroll
            for (int jj = KNN-1; jj > 0; --jj) {
                if (topv[jj] > topv[jj-1]) {
                    float tv_ = topv[jj]; topv[jj] = topv[jj-1]; topv[jj-1] = tv_;
                    int   ti_ = topi[jj]; topi[jj] = topi[jj-1]; topi[jj-1] = ti_;
                }
            }
        }
    }

    const float scale = 1.0f / sqrtf((float)DH);
    float agg[D];
    #pragma unroll
    for (int h = 0; h < NHEADS; h++) {
        float lg[KNN];
        #pragma unroll
        for (int kk = 0; kk < KNN; kk++) {
            const float4* kr = reinterpret_cast<const float4*>(sK + topi[kk]*DPAD + h*DH);
            float s = 0.f;
            #pragma unroll
            for (int d4 = 0; d4 < DH/4; d4++) {
                float4 kv = kr[d4];
                s += q[h*DH+4*d4]*kv.x + q[h*DH+4*d4+1]*kv.y + q[h*DH+4*d4+2]*kv.z + q[h*DH+4*d4+3]*kv.w;
            }
            lg[kk] = s * scale;
        }
        float mx = lg[0];
        #pragma unroll
        for (int kk = 1; kk < KNN; kk++) mx = fmaxf(mx, lg[kk]);
        float den = 0.f;
        #pragma unroll
        for (int kk = 0; kk < KNN; kk++) { lg[kk] = expf(lg[kk] - mx); den += lg[kk]; }
        const float inv = 1.0f / den;

        float ah[DH];
        #pragma unroll
        for (int dd = 0; dd < DH; dd++) ah[dd] = 0.f;
        #pragma unroll
        for (int kk = 0; kk < KNN; kk++) {
            const float w = lg[kk];
            const float4* vr = reinterpret_cast<const float4*>(sV + topi[kk]*DPAD + h*DH);
            #pragma unroll
            for (int d4 = 0; d4 < DH/4; d4++) {
                float4 vv = vr[d4];
                ah[4*d4]+=w*vv.x; ah[4*d4+1]+=w*vv.y; ah[4*d4+2]+=w*vv.z; ah[4*d4+3]+=w*vv.w;
            }
        }
        #pragma unroll
        for (int dd = 0; dd < DH; dd++) agg[h*DH+dd] = ah[dd]*inv;
    }

    #pragma unroll 1
    for (int cog = 0; cog < COUT; cog++) {
        float o0 = sBo[4*cog+0], o1 = sBo[4*cog+1], o2 = sBo[4*cog+2], o3 = sBo[4*cog+3];
        #pragma unroll
        for (int rr = 0; rr < R; rr++) {
            const float lv = loc[rr];
            const float4 w = reinterpret_cast<const float4*>(sWo + rr*CO)[cog];
            o0 += lv*w.x; o1 += lv*w.y; o2 += lv*w.z; o3 += lv*w.w;
        }
        #pragma unroll
        for (int dd = 0; dd < D; dd++) {
            const float av = agg[dd];
            const float4 w = reinterpret_cast<const float4*>(sWo + (R+dd)*CO)[cog];
            o0 += av*w.x; o1 += av*w.y; o2 += av*w.z; o3 += av*w.w;
        }
        if (Ahi) {
            // flat fc-input index: f = cog*1024 + (2i+si)*32 + (2j+sj)
            const size_t base = (size_t)b*32768 + (size_t)cog*1024 + (size_t)(2*i)*32 + 2*j;
            __half h0=__float2half_rn(o0), h1=__float2half_rn(o1);
            __half h2=__float2half_rn(o2), h3=__float2half_rn(o3);
            __half l0=__float2half_rn(o0-__half2float(h0));
            __half l1=__float2half_rn(o1-__half2float(h1));
            __half l2=__float2half_rn(o2-__half2float(h2));
            __half l3=__float2half_rn(o3-__half2float(h3));
            __half2 ph; ph.x=h0; ph.y=h1;
            __half2 pl; pl.x=l0; pl.y=l1;
            *reinterpret_cast<__half2*>(Ahi + base) = ph;
            *reinterpret_cast<__half2*>(Alo + base) = pl;
            ph.x=h2; ph.y=h3; pl.x=l2; pl.y=l3;
            *reinterpret_cast<__half2*>(Ahi + base + 32) = ph;
            *reinterpret_cast<__half2*>(Alo + base + 32) = pl;
        } else {
            float* yb = Y + ((size_t)(b*COUT + cog)*32 + 2*i)*32 + 2*j;
            *reinterpret_cast<float2*>(yb)      = make_float2(o0, o1);
            *reinterpret_cast<float2*>(yb + 32) = make_float2(o2, o3);
        }
    }
}

// =================================================================================
// W [32768,1024] fp32 -> transposed fp16 [1024][32768]
// =================================================================================
__global__ void __launch_bounds__(256) wconv_kernel(
    const float* __restrict__ W, __half* __restrict__ Th)
{
    __shared__ float t[32][33];
    const int k0 = blockIdx.x * 32, n0 = blockIdx.y * 32;
    const int tx = threadIdx.x, ty = threadIdx.y;   // (32,8)
    #pragma unroll
    for (int r = 0; r < 4; r++)
        t[ty + 8*r][tx] = W[(size_t)(k0 + ty + 8*r)*1024 + n0 + tx];
    __syncthreads();
    #pragma unroll
    for (int r = 0; r < 4; r++) {
        const int nn = ty + 8*r;
        Th[(size_t)(n0 + nn)*32768 + k0 + tx] = __float2half_rn(t[tx][nn]);
    }
}

// =================================================================================
// fc1 GEMM via mma.sync fp16 (A hi/lo split -> 2 products; W single fp16).
// CTA tile 128x128, 8 warps (warp 32x64), BK=32.
// cp.async 4-buffer pipeline, 3-stage lookahead, one __syncthreads per stage.
// grid = (8 Ntiles, 2 Mtiles, 9 Ksplits) = 144 CTAs (~one wave).
// smem row stride 40 halves (80B): ldmatrix + cp.async (80%16==0) conflict-free.
// =================================================================================
__global__ void __launch_bounds__(256) fc1_mma(
    const __half* __restrict__ Ahi, const __half* __restrict__ Alo,
    const __half* __restrict__ Wh, float* __restrict__ P)
{
    extern __shared__ char sm[];
    constexpr int KT = 32768;
    constexpr uint32_t TILE = 10240;            // 128 rows * 80 B
    constexpr uint32_t BUFS = 3*TILE;           // Ah | Al | Wh
    // 4 buffers: 4*30720 = 122880 B

    const int tid = threadIdx.x, wid = tid >> 5, lane = tid & 31;
    const int lr = lane >> 2, lc = lane & 3;
    const int tr = lane & 7, tq = lane >> 3;
    const int wm = wid & 3, wn = wid >> 2;
    const int m0 = blockIdx.y * 128, n0 = blockIdx.x * 128;
    const int ksp = blockIdx.z;
    const int sbase = ksp * 114;                // stage = 32 K-elems; 1024 stages total
    const int nstage = (ksp < 8) ? 114 : 112;

    const uint32_t smb = smem_u32(sm);
    const uint32_t rowA = (uint32_t)((tr + (tq & 1)*8)*80 + (tq >> 1)*16);
    const uint32_t rowB = (uint32_t)((tr + (tq >> 1)*8)*80 + (tq & 1)*16);

    const int r0g = tid >> 2, c0g = (tid & 3)*8;
    const __half* gAh = Ahi + (size_t)(m0 + r0g)*KT + c0g;
    const __half* gAl = Alo + (size_t)(m0 + r0g)*KT + c0g;
    const __half* gW  = Wh  + (size_t)(n0 + r0g)*KT + c0g;
    const size_t row64 = (size_t)64*KT;
    const uint32_t soff0 = (uint32_t)(r0g*80 + (tid & 3)*16);
    const uint32_t soff1 = soff0 + 64*80;

    float acc[2][8][4];
    #pragma unroll
    for (int mt = 0; mt < 2; mt++)
        #pragma unroll
        for (int nt = 0; nt < 8; nt++)
            #pragma unroll
            for (int e = 0; e < 4; e++) acc[mt][nt][e] = 0.f;

    // ---- pipeline prologue: stages 0..2 in flight ----
    #pragma unroll
    for (int p = 0; p < 3; p++) {
        const uint32_t b = smb + (uint32_t)p*BUFS;
        const int kk = (sbase + p)*32;
        cpa16(b + soff0,          gAh + kk);
        cpa16(b + soff1,          gAh + row64 + kk);
        cpa16(b + TILE + soff0,   gAl + kk);
        cpa16(b + TILE + soff1,   gAl + row64 + kk);
        cpa16(b + 2*TILE + soff0, gW + kk);
        cpa16(b + 2*TILE + soff1, gW + row64 + kk);
        CP_COMMIT();
    }

    for (int s = 0; s < nstage; s++) {
        CP_WAIT2();          // buffer s%4 data arrived (for this thread's copies)
        __syncthreads();     // ... and for everyone else's
        if (s + 3 < nstage) {
            const uint32_t b = smb + (uint32_t)((s + 3) & 3)*BUFS;
            const int kk = (sbase + s + 3)*32;
            cpa16(b + soff0,          gAh + kk);
            cpa16(b + soff1,          gAh + row64 + kk);
            cpa16(b + TILE + soff0,   gAl + kk);
            cpa16(b + TILE + soff1,   gAl + row64 + kk);
            cpa16(b + 2*TILE + soff0, gW + kk);
            cpa16(b + 2*TILE + soff1, gW + row64 + kk);
            CP_COMMIT();
        }
        const uint32_t base = smb + (uint32_t)(s & 3)*BUFS;
        const uint32_t aH = base + (uint32_t)(wm*32)*80 + rowA;
        const uint32_t aL = aH + TILE;
        const uint32_t bB = base + 2*TILE + (uint32_t)(wn*64)*80 + rowB;
        #pragma unroll
        for (int ks = 0; ks < 2; ks++) {
            const uint32_t kb = ks*32;
            uint32_t afh[2][4], afl[2][4], bfr[4][4];
            ldsm4(afh[0], aH + kb);            ldsm4(afh[1], aH + 16*80 + kb);
            ldsm4(afl[0], aL + kb);            ldsm4(afl[1], aL + 16*80 + kb);
            #pragma unroll
            for (int p = 0; p < 4; p++) ldsm4(bfr[p], bB + (uint32_t)(p*16)*80 + kb);
            #pragma unroll
            for (int mt = 0; mt < 2; mt++)
                #pragma unroll
                for (int nt = 0; nt < 8; nt++) {
                    uint32_t* bb = &bfr[nt >> 1][(nt & 1)*2];
                    MMA_F16(acc[mt][nt], afh[mt], bb);
                    MMA_F16(acc[mt][nt], afl[mt], bb);
                }
        }
    }

    float* Pp = P + (size_t)ksp * 262144;
    #pragma unroll
    for (int mt = 0; mt < 2; mt++) {
        const int r = m0 + wm*32 + mt*16 + lr;
        #pragma unroll
        for (int nt = 0; nt < 8; nt++) {
            const int cc = n0 + wn*64 + nt*8 + lc*2;
            *(float2*)(Pp + (size_t)r*1024 + cc)       = make_float2(acc[mt][nt][0], acc[mt][nt][1]);
            *(float2*)(Pp + (size_t)(r + 8)*1024 + cc) = make_float2(acc[mt][nt][2], acc[mt][nt][3]);
        }
    }
}

// fc1 partial reduction + bias + relu
__global__ void fc1_reduce(const float* __restrict__ P, const float* __restrict__ Bb,
                           float* __restrict__ O)
{
    const int idx = blockIdx.x * blockDim.x + threadIdx.x;   // 262144 total
    float s = Bb[idx & 1023];
    #pragma unroll
    for (int sp = 0; sp < 9; sp++) s += P[sp*262144 + idx];
    O[idx] = fmaxf(s, 0.f);
}

// fc2: [256,1024] @ [1024,10] + b
__global__ void fc2_kernel(const float* __restrict__ H, const float* __restrict__ W,
                           const float* __restrict__ Bb, float* __restrict__ out)
{
    const int b = blockIdx.x, tid = threadIdx.x;
    float acc[10];
    #pragma unroll
    for (int o = 0; o < 10; o++) acc[o] = 0.f;
    for (int k = tid; k < 1024; k += 128) {
        const float hv = H[b*1024 + k];
        const float* wr = W + k*10;
        #pragma unroll
        for (int o = 0; o < 10; o++) acc[o] += hv * wr[o];
    }
    __shared__ float red[4][10];
    #pragma unroll
    for (int o = 0; o < 10; o++) {
        #pragma unroll
        for (int off = 16; off; off >>= 1)
            acc[o] += __shfl_down_sync(0xffffffffu, acc[o], off);
    }
    if ((tid & 31) == 0) {
        #pragma unroll
        for (int o = 0; o < 10; o++) red[tid >> 5][o] = acc[o];
    }
    __syncthreads();
    if (tid < 10)
        out[b*10 + tid] = Bb[tid] + red[0][tid] + red[1][tid] + red[2][tid] + red[3][tid];
}

// =================================================================================
extern "C" void kernel_launch(void* const* d_in, const int* in_sizes, int n_in,
                              void* d_out, int out_size)
{
    const float* x    = (const float*)d_in[0];
    const float* w1c  = (const float*)d_in[1];
    const float* b1c  = (const float*)d_in[2];
    const float* w1q  = (const float*)d_in[3];
    const float* w1k  = (const float*)d_in[4];
    const float* w1v  = (const float*)d_in[5];
    const float* w1o  = (const float*)d_in[6];
    const float* b1o  = (const float*)d_in[7];
    const float* w2c  = (const float*)d_in[8];
    const float* b2c  = (const float*)d_in[9];
    const float* w2q  = (const float*)d_in[10];
    const float* w2k  = (const float*)d_in[11];
    const float* w2v  = (const float*)d_in[12];
    const float* w2o  = (const float*)d_in[13];
    const float* b2o  = (const float*)d_in[14];
    const float* fc1w = (const float*)d_in[15];
    const float* fc1b = (const float*)d_in[16];
    const float* fc2w = (const float*)d_in[17];
    const float* fc2b = (const float*)d_in[18];
    float* out = (float*)d_out;

    float *h1, *part, *fch;
    __half *ahi, *alo, *wh;
    cudaGetSymbolAddress((void**)&h1,   g_h1);
    cudaGetSymbolAddress((void**)&ahi,  g_Ahi);
    cudaGetSymbolAddress((void**)&alo,  g_Alo);
    cudaGetSymbolAddress((void**)&wh,   g_Wh);
    cudaGetSymbolAddress((void**)&part, g_part);
    cudaGetSymbolAddress((void**)&fch,  g_fc1);

    const int SM1 = (12*16 + 3*12*16 + (16+16)*64 + 16 + 64  + 2*256*(16+4)) * 4;
    const int SM2 = (64*32 + 3*64*32 + (32+32)*128 + 32 + 128 + 2*256*(32+4)) * 4;
    const int SMG = 4 * 3 * 10240;   // 4 buffers x (Ah|Al|Wh) x 10240B = 122880

    cudaFuncSetAttribute(attn_kernel<3,12,16,16,64>,
                         cudaFuncAttributeMaxDynamicSharedMemorySize, SM1);
    cudaFuncSetAttribute(attn_kernel<16,64,32,32,128>,
                         cudaFuncAttributeMaxDynamicSharedMemorySize, SM2);
    cudaFuncSetAttribute(fc1_mma,
                         cudaFuncAttributeMaxDynamicSharedMemorySize, SMG);

    wconv_kernel<<<dim3(1024, 32), dim3(32, 8)>>>(fc1w, wh);
    attn_kernel<3,12,16,16,64><<<256, 256, SM1>>>(x,  w1c, b1c, w1q, w1k, w1v, w1o, b1o,
                                                  h1, nullptr, nullptr);
    attn_kernel<16,64,32,32,128><<<256, 256, SM2>>>(h1, w2c, b2c, w2q, w2k, w2v, w2o, b2o,
                                                  nullptr, ahi, alo);
    fc1_mma<<<dim3(8, 2, 9), 256, SMG>>>(ahi, alo, wh, part);
    fc1_reduce<<<1024, 256>>>(part, fc1b, fch);
    fc2_kernel<<<256, 128>>>(fch, fc2w, fc2b, out);
}

// round 10
// speedup vs baseline: 1.6800x; 1.0731x over previous
#include <cuda_runtime.h>
#include <cuda_bf16.h>
#include <cuda_fp16.h>
#include <cstdint>
#include <stdint.h>
#include <math.h>

// ---------------- scratch (device globals; no allocation allowed) ----------------
__device__ float g_h1[256*16*32*32];        // layer1 output [B,16,32,32]
__device__ __half g_Ahi[256*32768];         // fc input, fp16 hi
__device__ __half g_Alo[256*32768];         // fc input, fp16 lo residual
__device__ __half g_Wh[1024ull*32768];      // fc1 weight TRANSPOSED [N,K], fp16
__device__ float g_part[18*256*1024];       // fc1 split-K partials
__device__ float g_fc1[256*1024];           // fc1 output (post relu)

__device__ __forceinline__ uint32_t smem_u32(const void* p) {
    uint32_t a;
    asm("{ .reg .u64 t; cvta.to.shared.u64 t, %1; cvt.u32.u64 %0, t; }" : "=r"(a) : "l"(p));
    return a;
}
__device__ __forceinline__ void ldsm4(uint32_t* r, uint32_t addr) {
    asm volatile("ldmatrix.sync.aligned.m8n8.x4.shared.b16 {%0,%1,%2,%3}, [%4];"
                 : "=r"(r[0]), "=r"(r[1]), "=r"(r[2]), "=r"(r[3]) : "r"(addr));
}
__device__ __forceinline__ void cpa16(uint32_t dst, const void* src) {
    asm volatile("cp.async.ca.shared.global [%0], [%1], 16;" :: "r"(dst), "l"(src));
}
#define CP_COMMIT() asm volatile("cp.async.commit_group;" ::: "memory")
#define CP_WAIT1()  asm volatile("cp.async.wait_group 1;" ::: "memory")
#define MMA_F16(d, a, bb)                                                                      \
    asm volatile("mma.sync.aligned.m16n8k16.row.col.f32.f16.f16.f32 "                          \
        "{%0,%1,%2,%3}, {%4,%5,%6,%7}, {%8,%9}, {%0,%1,%2,%3};"                                \
        : "+f"((d)[0]), "+f"((d)[1]), "+f"((d)[2]), "+f"((d)[3])                               \
        : "r"((a)[0]), "r"((a)[1]), "r"((a)[2]), "r"((a)[3]), "r"((bb)[0]), "r"((bb)[1]))

// =================================================================================
// Fused ConvNN-branch attention layer. grid = B, block = 256 (one thread/token).
// If Ahi/Alo non-null (layer 2), emits fp16 hi/lo split of output instead of fp32.
// OCC: 2 for layer 1 (49KB smem), 1 for layer 2 (137KB smem).
// =================================================================================
template<int CIN, int CU, int R, int D, int CO, int OCC>
__global__ void __launch_bounds__(256, OCC) attn_kernel(
    const float* __restrict__ X,
    const float* __restrict__ Wc, const float* __restrict__ Bc,
    const float* __restrict__ Wq, const float* __restrict__ Wk, const float* __restrict__ Wv,
    const float* __restrict__ Wo, const float* __restrict__ Bo,
    float* __restrict__ Y, __half* __restrict__ Ahi, __half* __restrict__ Alo)
{
    constexpr int NTOK = 256;
    constexpr int NHEADS = 4;
    constexpr int DH = D / NHEADS;
    constexpr int KNN = 9;
    constexpr int DPAD = D + 4;
    constexpr int COUT = CO / 4;

    extern __shared__ float smem[];
    float* sWc = smem;
    float* sWq = sWc + CU*R;
    float* sWk = sWq + CU*D;
    float* sWv = sWk + CU*D;
    float* sWo = sWv + CU*D;
    float* sBc = sWo + (R+D)*CO;
    float* sBo = sBc + R;
    float* sK  = sBo + CO;
    float* sV  = sK + NTOK*DPAD;

    const int b = blockIdx.x;
    const int n = threadIdx.x;

    for (int idx = n; idx < CU*R; idx += NTOK) sWc[idx] = Wc[idx];
    for (int idx = n; idx < CU*D; idx += NTOK) { sWq[idx]=Wq[idx]; sWk[idx]=Wk[idx]; sWv[idx]=Wv[idx]; }
    for (int idx = n; idx < (R+D)*CO; idx += NTOK) sWo[idx] = Wo[idx];
    if (n < R)  sBc[n] = Bc[n];
    if (n < CO) sBo[n] = Bo[n];
    __syncthreads();

    const int i = n >> 4;
    const int j = n & 15;

    float q[D], ka[D], va[D], loc[R];
    #pragma unroll
    for (int dd = 0; dd < D; dd++) { q[dd]=0.f; ka[dd]=0.f; va[dd]=0.f; }
    #pragma unroll
    for (int rr = 0; rr < R; rr++) loc[rr] = sBc[rr];

    #pragma unroll 4
    for (int c = 0; c < CU; c++) {
        const int ch = c >> 2, si = (c >> 1) & 1, sj = c & 1;
        const float tv = X[((b*CIN + ch)*32 + 2*i + si)*32 + 2*j + sj];
        const float4* wq4 = reinterpret_cast<const float4*>(sWq + c*D);
        const float4* wk4 = reinterpret_cast<const float4*>(sWk + c*D);
        const float4* wv4 = reinterpret_cast<const float4*>(sWv + c*D);
        const float4* wc4 = reinterpret_cast<const float4*>(sWc + c*R);
        #pragma unroll
        for (int d4 = 0; d4 < D/4; d4++) {
            float4 w;
            w = wq4[d4]; q[4*d4]+=tv*w.x;  q[4*d4+1]+=tv*w.y;  q[4*d4+2]+=tv*w.z;  q[4*d4+3]+=tv*w.w;
            w = wk4[d4]; ka[4*d4]+=tv*w.x; ka[4*d4+1]+=tv*w.y; ka[4*d4+2]+=tv*w.z; ka[4*d4+3]+=tv*w.w;
            w = wv4[d4]; va[4*d4]+=tv*w.x; va[4*d4+1]+=tv*w.y; va[4*d4+2]+=tv*w.z; va[4*d4+3]+=tv*w.w;
        }
        #pragma unroll
        for (int r4 = 0; r4 < R/4; r4++) {
            float4 w = wc4[r4];
            loc[4*r4]+=tv*w.x; loc[4*r4+1]+=tv*w.y; loc[4*r4+2]+=tv*w.z; loc[4*r4+3]+=tv*w.w;
        }
    }
    #pragma unroll
    for (int rr = 0; rr < R; rr++) loc[rr] = fmaxf(loc[rr], 0.f);
    #pragma unroll
    for (int d4 = 0; d4 < D/4; d4++) {
        reinterpret_cast<float4*>(sK + n*DPAD)[d4] = make_float4(ka[4*d4],ka[4*d4+1],ka[4*d4+2],ka[4*d4+3]);
        reinterpret_cast<float4*>(sV + n*DPAD)[d4] = make_float4(va[4*d4],va[4*d4+1],va[4*d4+2],va[4*d4+3]);
    }
    __syncthreads();

    float topv[KNN]; int topi[KNN];
    #pragma unroll
    for (int kk = 0; kk < KNN; kk++) { topv[kk] = -1e30f; topi[kk] = 0; }

    for (int m = 0; m < NTOK; m++) {
        const float4* kp = reinterpret_cast<const float4*>(sK + m*DPAD);
        float dot = 0.f;
        #pragma unroll
        for (int d4 = 0; d4 < D/4; d4++) {
            float4 kv = kp[d4];
            dot += q[4*d4]*kv.x + q[4*d4+1]*kv.y + q[4*d4+2]*kv.z + q[4*d4+3]*kv.w;
        }
        if (dot > topv[KNN-1]) {
            topv[KNN-1] = dot; topi[KNN-1] = m;
            #pragma unroll
            for (int jj = KNN-1; jj > 0; --jj) {
                if (topv[jj] > topv[jj-1]) {
                    float tv_ = topv[jj]; topv[jj] = topv[jj-1]; topv[jj-1] = tv_;
                    int   ti_ = topi[jj]; topi[jj] = topi[jj-1]; topi[jj-1] = ti_;
                }
            }
        }
    }

    const float scale = 1.0f / sqrtf((float)DH);
    float agg[D];
    #pragma unroll
    for (int h = 0; h < NHEADS; h++) {
        float lg[KNN];
        #pragma unroll
        for (int kk = 0; kk < KNN; kk++) {
            const float4* kr = reinterpret_cast<const float4*>(sK + topi[kk]*DPAD + h*DH);
            float s = 0.f;
            #pragma unroll
            for (int d4 = 0; d4 < DH/4; d4++) {
                float4 kv = kr[d4];
                s += q[h*DH+4*d4]*kv.x + q[h*DH+4*d4+1]*kv.y + q[h*DH+4*d4+2]*kv.z + q[h*DH+4*d4+3]*kv.w;
            }
            lg[kk] = s * scale;
        }
        float mx = lg[0];
        #pragma unroll
        for (int kk = 1; kk < KNN; kk++) mx = fmaxf(mx, lg[kk]);
        float den = 0.f;
        #pragma unroll
        for (int kk = 0; kk < KNN; kk++) { lg[kk] = expf(lg[kk] - mx); den += lg[kk]; }
        const float inv = 1.0f / den;

        float ah[DH];
        #pragma unroll
        for (int dd = 0; dd < DH; dd++) ah[dd] = 0.f;
        #pragma unroll
        for (int kk = 0; kk < KNN; kk++) {
            const float w = lg[kk];
            const float4* vr = reinterpret_cast<const float4*>(sV + topi[kk]*DPAD + h*DH);
            #pragma unroll
            for (int d4 = 0; d4 < DH/4; d4++) {
                float4 vv = vr[d4];
                ah[4*d4]+=w*vv.x; ah[4*d4+1]+=w*vv.y; ah[4*d4+2]+=w*vv.z; ah[4*d4+3]+=w*vv.w;
            }
        }
        #pragma unroll
        for (int dd = 0; dd < DH; dd++) agg[h*DH+dd] = ah[dd]*inv;
    }

    #pragma unroll 1
    for (int cog = 0; cog < COUT; cog++) {
        float o0 = sBo[4*cog+0], o1 = sBo[4*cog+1], o2 = sBo[4*cog+2], o3 = sBo[4*cog+3];
        #pragma unroll
        for (int rr = 0; rr < R; rr++) {
            const float lv = loc[rr];
            const float4 w = reinterpret_cast<const float4*>(sWo + rr*CO)[cog];
            o0 += lv*w.x; o1 += lv*w.y; o2 += lv*w.z; o3 += lv*w.w;
        }
        #pragma unroll
        for (int dd = 0; dd < D; dd++) {
            const float av = agg[dd];
            const float4 w = reinterpret_cast<const float4*>(sWo + (R+dd)*CO)[cog];
            o0 += av*w.x; o1 += av*w.y; o2 += av*w.z; o3 += av*w.w;
        }
        if (Ahi) {
            // flat fc-input index: f = cog*1024 + (2i+si)*32 + (2j+sj)
            const size_t base = (size_t)b*32768 + (size_t)cog*1024 + (size_t)(2*i)*32 + 2*j;
            __half h0=__float2half_rn(o0), h1=__float2half_rn(o1);
            __half h2=__float2half_rn(o2), h3=__float2half_rn(o3);
            __half l0=__float2half_rn(o0-__half2float(h0));
            __half l1=__float2half_rn(o1-__half2float(h1));
            __half l2=__float2half_rn(o2-__half2float(h2));
            __half l3=__float2half_rn(o3-__half2float(h3));
            __half2 ph; ph.x=h0; ph.y=h1;
            __half2 pl; pl.x=l0; pl.y=l1;
            *reinterpret_cast<__half2*>(Ahi + base) = ph;
            *reinterpret_cast<__half2*>(Alo + base) = pl;
            ph.x=h2; ph.y=h3; pl.x=l2; pl.y=l3;
            *reinterpret_cast<__half2*>(Ahi + base + 32) = ph;
            *reinterpret_cast<__half2*>(Alo + base + 32) = pl;
        } else {
            float* yb = Y + ((size_t)(b*COUT + cog)*32 + 2*i)*32 + 2*j;
            *reinterpret_cast<float2*>(yb)      = make_float2(o0, o1);
            *reinterpret_cast<float2*>(yb + 32) = make_float2(o2, o3);
        }
    }
}

// =================================================================================
// W [32768,1024] fp32 -> transposed fp16 [1024][32768]
// =================================================================================
__global__ void __launch_bounds__(256) wconv_kernel(
    const float* __restrict__ W, __half* __restrict__ Th)
{
    __shared__ float t[32][33];
    const int k0 = blockIdx.x * 32, n0 = blockIdx.y * 32;
    const int tx = threadIdx.x, ty = threadIdx.y;   // (32,8)
    #pragma unroll
    for (int r = 0; r < 4; r++)
        t[ty + 8*r][tx] = W[(size_t)(k0 + ty + 8*r)*1024 + n0 + tx];
    __syncthreads();
    #pragma unroll
    for (int r = 0; r < 4; r++) {
        const int nn = ty + 8*r;
        Th[(size_t)(n0 + nn)*32768 + k0 + tx] = __float2half_rn(t[tx][nn]);
    }
}

// =================================================================================
// fc1 GEMM via mma.sync fp16 (A hi/lo split -> 2 products; W single fp16).
// CTA tile 128x128, 8 warps (warp 32x64), BK=32.
// cp.async 3-buffer pipeline, 2-stage lookahead, 2 CTAs/SM (92KB smem, 128 regs).
// grid = (8 Ntiles, 2 Mtiles, 18 Ksplits) = 288 CTAs, all resident at occ 2.
// smem row stride 40 halves (80B): ldmatrix + cp.async conflict-free.
// =================================================================================
__global__ void __launch_bounds__(256, 2) fc1_mma(
    const __half* __restrict__ Ahi, const __half* __restrict__ Alo,
    const __half* __restrict__ Wh, float* __restrict__ P)
{
    extern __shared__ char sm[];
    constexpr int KT = 32768;
    constexpr uint32_t TILE = 10240;            // 128 rows * 80 B
    constexpr uint32_t BUFS = 3*TILE;           // Ah | Al | Wh
    // 3 buffers: 3*30720 = 92160 B -> 2 CTAs/SM

    const int tid = threadIdx.x, wid = tid >> 5, lane = tid & 31;
    const int lr = lane >> 2, lc = lane & 3;
    const int tr = lane & 7, tq = lane >> 3;
    const int wm = wid & 3, wn = wid >> 2;
    const int m0 = blockIdx.y * 128, n0 = blockIdx.x * 128;
    const int ksp = blockIdx.z;
    // 1024 stages over 18 splits: first 16 splits get 57, last 2 get 56
    const int sbase  = (ksp < 16) ? ksp*57 : 912 + (ksp - 16)*56;
    const int nstage = (ksp < 16) ? 57 : 56;

    const uint32_t smb = smem_u32(sm);
    const uint32_t rowA = (uint32_t)((tr + (tq & 1)*8)*80 + (tq >> 1)*16);
    const uint32_t rowB = (uint32_t)((tr + (tq >> 1)*8)*80 + (tq & 1)*16);

    const int r0g = tid >> 2, c0g = (tid & 3)*8;
    const __half* gAh = Ahi + (size_t)(m0 + r0g)*KT + c0g;
    const __half* gAl = Alo + (size_t)(m0 + r0g)*KT + c0g;
    const __half* gW  = Wh  + (size_t)(n0 + r0g)*KT + c0g;
    const size_t row64 = (size_t)64*KT;
    const uint32_t soff0 = (uint32_t)(r0g*80 + (tid & 3)*16);
    const uint32_t soff1 = soff0 + 64*80;

    float acc[2][8][4];
    #pragma unroll
    for (int mt = 0; mt < 2; mt++)
        #pragma unroll
        for (int nt = 0; nt < 8; nt++)
            #pragma unroll
            for (int e = 0; e < 4; e++) acc[mt][nt][e] = 0.f;

    // ---- pipeline prologue: stages 0..1 in flight ----
    #pragma unroll
    for (int p = 0; p < 2; p++) {
        const uint32_t b = smb + (uint32_t)p*BUFS;
        const int kk = (sbase + p)*32;
        cpa16(b + soff0,          gAh + kk);
        cpa16(b + soff1,          gAh + row64 + kk);
        cpa16(b + TILE + soff0,   gAl + kk);
        cpa16(b + TILE + soff1,   gAl + row64 + kk);
        cpa16(b + 2*TILE + soff0, gW + kk);
        cpa16(b + 2*TILE + soff1, gW + row64 + kk);
        CP_COMMIT();
    }

    int bufc = 0, bufn = 2;   // compute buffer, next-fill buffer
    for (int s = 0; s < nstage; s++) {
        CP_WAIT1();          // buffer for stage s arrived (this thread's copies)
        __syncthreads();     // ... and for everyone else's; stage s-1 fully consumed
        if (s + 2 < nstage) {
            const uint32_t b = smb + (uint32_t)bufn*BUFS;
            const int kk = (sbase + s + 2)*32;
            cpa16(b + soff0,          gAh + kk);
            cpa16(b + soff1,          gAh + row64 + kk);
            cpa16(b + TILE + soff0,   gAl + kk);
            cpa16(b + TILE + soff1,   gAl + row64 + kk);
            cpa16(b + 2*TILE + soff0, gW + kk);
            cpa16(b + 2*TILE + soff1, gW + row64 + kk);
            CP_COMMIT();
        }
        const uint32_t base = smb + (uint32_t)bufc*BUFS;
        bufc = (bufc + 1 == 3) ? 0 : bufc + 1;
        bufn = (bufn + 1 == 3) ? 0 : bufn + 1;
        const uint32_t aH = base + (uint32_t)(wm*32)*80 + rowA;
        const uint32_t aL = aH + TILE;
        const uint32_t bB = base + 2*TILE + (uint32_t)(wn*64)*80 + rowB;
        #pragma unroll
        for (int ks = 0; ks < 2; ks++) {
            const uint32_t kb = ks*32;
            uint32_t afh[2][4], afl[2][4], bfr[4][4];
            ldsm4(afh[0], aH + kb);            ldsm4(afh[1], aH + 16*80 + kb);
            ldsm4(afl[0], aL + kb);            ldsm4(afl[1], aL + 16*80 + kb);
            #pragma unroll
            for (int p = 0; p < 4; p++) ldsm4(bfr[p], bB + (uint32_t)(p*16)*80 + kb);
            #pragma unroll
            for (int mt = 0; mt < 2; mt++)
                #pragma unroll
                for (int nt = 0; nt < 8; nt++) {
                    uint32_t* bb = &bfr[nt >> 1][(nt & 1)*2];
                    MMA_F16(acc[mt][nt], afh[mt], bb);
                    MMA_F16(acc[mt][nt], afl[mt], bb);
                }
        }
    }

    float* Pp = P + (size_t)ksp * 262144;
    #pragma unroll
    for (int mt = 0; mt < 2; mt++) {
        const int r = m0 + wm*32 + mt*16 + lr;
        #pragma unroll
        for (int nt = 0; nt < 8; nt++) {
            const int cc = n0 + wn*64 + nt*8 + lc*2;
            *(float2*)(Pp + (size_t)r*1024 + cc)       = make_float2(acc[mt][nt][0], acc[mt][nt][1]);
            *(float2*)(Pp + (size_t)(r + 8)*1024 + cc) = make_float2(acc[mt][nt][2], acc[mt][nt][3]);
        }
    }
}

// fc1 partial reduction + bias + relu
__global__ void fc1_reduce(const float* __restrict__ P, const float* __restrict__ Bb,
                           float* __restrict__ O)
{
    const int idx = blockIdx.x * blockDim.x + threadIdx.x;   // 262144 total
    float s = Bb[idx & 1023];
    #pragma unroll
    for (int sp = 0; sp < 18; sp++) s += P[sp*262144 + idx];
    O[idx] = fmaxf(s, 0.f);
}

// fc2: [256,1024] @ [1024,10] + b
__global__ void fc2_kernel(const float* __restrict__ H, const float* __restrict__ W,
                           const float* __restrict__ Bb, float* __restrict__ out)
{
    const int b = blockIdx.x, tid = threadIdx.x;
    float acc[10];
    #pragma unroll
    for (int o = 0; o < 10; o++) acc[o] = 0.f;
    for (int k = tid; k < 1024; k += 128) {
        const float hv = H[b*1024 + k];
        const float* wr = W + k*10;
        #pragma unroll
        for (int o = 0; o < 10; o++) acc[o] += hv * wr[o];
    }
    __shared__ float red[4][10];
    #pragma unroll
    for (int o = 0; o < 10; o++) {
        #pragma unroll
        for (int off = 16; off; off >>= 1)
            acc[o] += __shfl_down_sync(0xffffffffu, acc[o], off);
    }
    if ((tid & 31) == 0) {
        #pragma unroll
        for (int o = 0; o < 10; o++) red[tid >> 5][o] = acc[o];
    }
    __syncthreads();
    if (tid < 10)
        out[b*10 + tid] = Bb[tid] + red[0][tid] + red[1][tid] + red[2][tid] + red[3][tid];
}

// =================================================================================
extern "C" void kernel_launch(void* const* d_in, const int* in_sizes, int n_in,
                              void* d_out, int out_size)
{
    const float* x    = (const float*)d_in[0];
    const float* w1c  = (const float*)d_in[1];
    const float* b1c  = (const float*)d_in[2];
    const float* w1q  = (const float*)d_in[3];
    const float* w1k  = (const float*)d_in[4];
    const float* w1v  = (const float*)d_in[5];
    const float* w1o  = (const float*)d_in[6];
    const float* b1o  = (const float*)d_in[7];
    const float* w2c  = (const float*)d_in[8];
    const float* b2c  = (const float*)d_in[9];
    const float* w2q  = (const float*)d_in[10];
    const float* w2k  = (const float*)d_in[11];
    const float* w2v  = (const float*)d_in[12];
    const float* w2o  = (const float*)d_in[13];
    const float* b2o  = (const float*)d_in[14];
    const float* fc1w = (const float*)d_in[15];
    const float* fc1b = (const float*)d_in[16];
    const float* fc2w = (const float*)d_in[17];
    const float* fc2b = (const float*)d_in[18];
    float* out = (float*)d_out;

    float *h1, *part, *fch;
    __half *ahi, *alo, *wh;
    cudaGetSymbolAddress((void**)&h1,   g_h1);
    cudaGetSymbolAddress((void**)&ahi,  g_Ahi);
    cudaGetSymbolAddress((void**)&alo,  g_Alo);
    cudaGetSymbolAddress((void**)&wh,   g_Wh);
    cudaGetSymbolAddress((void**)&part, g_part);
    cudaGetSymbolAddress((void**)&fch,  g_fc1);

    const int SM1 = (12*16 + 3*12*16 + (16+16)*64 + 16 + 64  + 2*256*(16+4)) * 4;
    const int SM2 = (64*32 + 3*64*32 + (32+32)*128 + 32 + 128 + 2*256*(32+4)) * 4;
    const int SMG = 3 * 3 * 10240;   // 3 buffers x (Ah|Al|Wh) x 10240B = 92160

    cudaFuncSetAttribute(attn_kernel<3,12,16,16,64,2>,
                         cudaFuncAttributeMaxDynamicSharedMemorySize, SM1);
    cudaFuncSetAttribute(attn_kernel<16,64,32,32,128,1>,
                         cudaFuncAttributeMaxDynamicSharedMemorySize, SM2);
    cudaFuncSetAttribute(fc1_mma,
                         cudaFuncAttributeMaxDynamicSharedMemorySize, SMG);

    wconv_kernel<<<dim3(1024, 32), dim3(32, 8)>>>(fc1w, wh);
    attn_kernel<3,12,16,16,64,2><<<256, 256, SM1>>>(x,  w1c, b1c, w1q, w1k, w1v, w1o, b1o,
                                                  h1, nullptr, nullptr);
    attn_kernel<16,64,32,32,128,1><<<256, 256, SM2>>>(h1, w2c, b2c, w2q, w2k, w2v, w2o, b2o,
                                                  nullptr, ahi, alo);
    fc1_mma<<<dim3(8, 2, 18), 256, SMG>>>(ahi, alo, wh, part);
    fc1_reduce<<<1024, 256>>>(part, fc1b, fch);
    fc2_kernel<<<256, 128>>>(fch, fc2w, fc2b, out);
}

// round 12
// speedup vs baseline: 1.7384x; 1.0347x over previous
#include <cuda_runtime.h>
#include <cuda_bf16.h>
#include <cuda_fp16.h>
#include <cstdint>
#include <stdint.h>
#include <math.h>

// ---------------- scratch (device globals; no allocation allowed) ----------------
__device__ float g_h1[256*16*32*32];        // layer1 output [B,16,32,32]
__device__ __half g_Ahi[256*32768];         // fc input, fp16 hi
__device__ __half g_Alo[256*32768];         // fc input, fp16 lo residual
__device__ __half g_Wh[1024ull*32768];      // fc1 weight TRANSPOSED [N,K], fp16
__device__ float g_part[18*256*1024];       // fc1 split-K partials
__device__ float g_fc1[256*1024];           // fc1 output (post relu)

__device__ __forceinline__ uint32_t smem_u32(const void* p) {
    uint32_t a;
    asm("{ .reg .u64 t; cvta.to.shared.u64 t, %1; cvt.u32.u64 %0, t; }" : "=r"(a) : "l"(p));
    return a;
}
__device__ __forceinline__ void ldsm4(uint32_t* r, uint32_t addr) {
    asm volatile("ldmatrix.sync.aligned.m8n8.x4.shared.b16 {%0,%1,%2,%3}, [%4];"
                 : "=r"(r[0]), "=r"(r[1]), "=r"(r[2]), "=r"(r[3]) : "r"(addr));
}
__device__ __forceinline__ void cpa16(uint32_t dst, const void* src) {
    asm volatile("cp.async.ca.shared.global [%0], [%1], 16;" :: "r"(dst), "l"(src));
}
#define CP_COMMIT() asm volatile("cp.async.commit_group;" ::: "memory")
#define CP_WAIT1()  asm volatile("cp.async.wait_group 1;" ::: "memory")
#define MMA_F16(d, a, bb)                                                                      \
    asm volatile("mma.sync.aligned.m16n8k16.row.col.f32.f16.f16.f32 "                          \
        "{%0,%1,%2,%3}, {%4,%5,%6,%7}, {%8,%9}, {%0,%1,%2,%3};"                                \
        : "+f"((d)[0]), "+f"((d)[1]), "+f"((d)[2]), "+f"((d)[3])                               \
        : "r"((a)[0]), "r"((a)[1]), "r"((a)[2]), "r"((a)[3]), "r"((bb)[0]), "r"((bb)[1]))

// =================================================================================
// Fused ConvNN-branch attention layer. grid = B, block = 256 (one thread/token).
// If Ahi/Alo non-null (layer 2), emits fp16 hi/lo split of output instead of fp32.
// OPT2=1 (layer 2): Wo overlaid on projection weights AFTER phase B; q and loc are
// computed in phase B and carried in registers (nothing reads proj weights later).
// =================================================================================
template<int CIN, int CU, int R, int D, int CO, int OCC, int OPT2>
__global__ void __launch_bounds__(256, OCC) attn_kernel(
    const float* __restrict__ X,
    const float* __restrict__ Wc, const float* __restrict__ Bc,
    const float* __restrict__ Wq, const float* __restrict__ Wk, const float* __restrict__ Wv,
    const float* __restrict__ Wo, const float* __restrict__ Bo,
    float* __restrict__ Y, __half* __restrict__ Ahi, __half* __restrict__ Alo)
{
    constexpr int NTOK = 256;
    constexpr int NHEADS = 4;
    constexpr int DH = D / NHEADS;
    constexpr int KNN = 9;
    constexpr int DPAD = D + 4;
    constexpr int COUT = CO / 4;
    constexpr int PROJ = CU*R + 3*CU*D;
    constexpr int WOSZ = (R + D)*CO;
    constexpr int REG0 = OPT2 ? (PROJ > WOSZ ? PROJ : WOSZ) : (PROJ + WOSZ);

    extern __shared__ float smem[];
    float* sWc = smem;
    float* sWq = sWc + CU*R;
    float* sWk = sWq + CU*D;
    float* sWv = sWk + CU*D;
    float* sWo = OPT2 ? smem : (sWv + CU*D);
    float* sBc = smem + REG0;
    float* sBo = sBc + R;
    float* sK  = sBo + CO;
    float* sV  = sK + NTOK*DPAD;

    const int b = blockIdx.x;
    const int n = threadIdx.x;

    for (int idx = n; idx < CU*R; idx += NTOK) sWc[idx] = Wc[idx];
    for (int idx = n; idx < CU*D; idx += NTOK) { sWq[idx]=Wq[idx]; sWk[idx]=Wk[idx]; sWv[idx]=Wv[idx]; }
    if (!OPT2)
        for (int idx = n; idx < WOSZ; idx += NTOK) sWo[idx] = Wo[idx];
    if (n < R)  sBc[n] = Bc[n];
    if (n < CO) sBo[n] = Bo[n];
    __syncthreads();

    const int i = n >> 4;
    const int j = n & 15;

    float q[D], loc[R];

    if (OPT2) {
        // ---- pass 1: k/v projections only (64 live floats) ----
        {
            float ka[D], va[D];
            #pragma unroll
            for (int dd = 0; dd < D; dd++) { ka[dd]=0.f; va[dd]=0.f; }
            #pragma unroll 4
            for (int c = 0; c < CU; c++) {
                const int ch = c >> 2, si = (c >> 1) & 1, sj = c & 1;
                const float tv = X[((b*CIN + ch)*32 + 2*i + si)*32 + 2*j + sj];
                const float4* wk4 = reinterpret_cast<const float4*>(sWk + c*D);
                const float4* wv4 = reinterpret_cast<const float4*>(sWv + c*D);
                #pragma unroll
                for (int d4 = 0; d4 < D/4; d4++) {
                    float4 w;
                    w = wk4[d4]; ka[4*d4]+=tv*w.x; ka[4*d4+1]+=tv*w.y; ka[4*d4+2]+=tv*w.z; ka[4*d4+3]+=tv*w.w;
                    w = wv4[d4]; va[4*d4]+=tv*w.x; va[4*d4+1]+=tv*w.y; va[4*d4+2]+=tv*w.z; va[4*d4+3]+=tv*w.w;
                }
            }
            #pragma unroll
            for (int d4 = 0; d4 < D/4; d4++) {
                reinterpret_cast<float4*>(sK + n*DPAD)[d4] = make_float4(ka[4*d4],ka[4*d4+1],ka[4*d4+2],ka[4*d4+3]);
                reinterpret_cast<float4*>(sV + n*DPAD)[d4] = make_float4(va[4*d4],va[4*d4+1],va[4*d4+2],va[4*d4+3]);
            }
        }
        // ---- pass 2: q + loc projections (kept in registers through C/D) ----
        #pragma unroll
        for (int dd = 0; dd < D; dd++) q[dd] = 0.f;
        #pragma unroll
        for (int rr = 0; rr < R; rr++) loc[rr] = sBc[rr];
        #pragma unroll 4
        for (int c = 0; c < CU; c++) {
            const int ch = c >> 2, si = (c >> 1) & 1, sj = c & 1;
            const float tv = X[((b*CIN + ch)*32 + 2*i + si)*32 + 2*j + sj];
            const float4* wq4 = reinterpret_cast<const float4*>(sWq + c*D);
            const float4* wc4 = reinterpret_cast<const float4*>(sWc + c*R);
            #pragma unroll
            for (int d4 = 0; d4 < D/4; d4++) {
                float4 w = wq4[d4];
                q[4*d4]+=tv*w.x; q[4*d4+1]+=tv*w.y; q[4*d4+2]+=tv*w.z; q[4*d4+3]+=tv*w.w;
            }
            #pragma unroll
            for (int r4 = 0; r4 < R/4; r4++) {
                float4 w = wc4[r4];
                loc[4*r4]+=tv*w.x; loc[4*r4+1]+=tv*w.y; loc[4*r4+2]+=tv*w.z; loc[4*r4+3]+=tv*w.w;
            }
        }
        #pragma unroll
        for (int rr = 0; rr < R; rr++) loc[rr] = fmaxf(loc[rr], 0.f);
        __syncthreads();   // all proj-weight reads done; K/V visible
        // overlay: reload Wo into region0 (latency hidden behind phases C/D)
        for (int idx = n; idx < WOSZ; idx += NTOK) sWo[idx] = Wo[idx];
    } else {
        float ka[D], va[D];
        #pragma unroll
        for (int dd = 0; dd < D; dd++) { q[dd]=0.f; ka[dd]=0.f; va[dd]=0.f; }
        #pragma unroll
        for (int rr = 0; rr < R; rr++) loc[rr] = sBc[rr];

        #pragma unroll 4
        for (int c = 0; c < CU; c++) {
            const int ch = c >> 2, si = (c >> 1) & 1, sj = c & 1;
            const float tv = X[((b*CIN + ch)*32 + 2*i + si)*32 + 2*j + sj];
            const float4* wq4 = reinterpret_cast<const float4*>(sWq + c*D);
            const float4* wk4 = reinterpret_cast<const float4*>(sWk + c*D);
            const float4* wv4 = reinterpret_cast<const float4*>(sWv + c*D);
            const float4* wc4 = reinterpret_cast<const float4*>(sWc + c*R);
            #pragma unroll
            for (int d4 = 0; d4 < D/4; d4++) {
                float4 w;
                w = wq4[d4]; q[4*d4]+=tv*w.x;  q[4*d4+1]+=tv*w.y;  q[4*d4+2]+=tv*w.z;  q[4*d4+3]+=tv*w.w;
                w = wk4[d4]; ka[4*d4]+=tv*w.x; ka[4*d4+1]+=tv*w.y; ka[4*d4+2]+=tv*w.z; ka[4*d4+3]+=tv*w.w;
                w = wv4[d4]; va[4*d4]+=tv*w.x; va[4*d4+1]+=tv*w.y; va[4*d4+2]+=tv*w.z; va[4*d4+3]+=tv*w.w;
            }
            #pragma unroll
            for (int r4 = 0; r4 < R/4; r4++) {
                float4 w = wc4[r4];
                loc[4*r4]+=tv*w.x; loc[4*r4+1]+=tv*w.y; loc[4*r4+2]+=tv*w.z; loc[4*r4+3]+=tv*w.w;
            }
        }
        #pragma unroll
        for (int rr = 0; rr < R; rr++) loc[rr] = fmaxf(loc[rr], 0.f);
        #pragma unroll
        for (int d4 = 0; d4 < D/4; d4++) {
            reinterpret_cast<float4*>(sK + n*DPAD)[d4] = make_float4(ka[4*d4],ka[4*d4+1],ka[4*d4+2],ka[4*d4+3]);
            reinterpret_cast<float4*>(sV + n*DPAD)[d4] = make_float4(va[4*d4],va[4*d4+1],va[4*d4+2],va[4*d4+3]);
        }
        __syncthreads();
    }

    // ---- phase C: full-d sim over all tokens + streaming top-9 ----
    float topv[KNN]; int topi[KNN];
    #pragma unroll
    for (int kk = 0; kk < KNN; kk++) { topv[kk] = -1e30f; topi[kk] = 0; }

    for (int m = 0; m < NTOK; m++) {
        const float4* kp = reinterpret_cast<const float4*>(sK + m*DPAD);
        float dot = 0.f;
        #pragma unroll
        for (int d4 = 0; d4 < D/4; d4++) {
            float4 kv = kp[d4];
            dot += q[4*d4]*kv.x + q[4*d4+1]*kv.y + q[4*d4+2]*kv.z + q[4*d4+3]*kv.w;
        }
        if (dot > topv[KNN-1]) {
            topv[KNN-1] = dot; topi[KNN-1] = m;
            #pragma unroll
            for (int jj = KNN-1; jj > 0; --jj) {
                if (topv[jj] > topv[jj-1]) {
                    float tv_ = topv[jj]; topv[jj] = topv[jj-1]; topv[jj-1] = tv_;
                    int   ti_ = topi[jj]; topi[jj] = topi[jj-1]; topi[jj-1] = ti_;
                }
            }
        }
    }

    // ---- phase D: per-head softmax attention over 9 neighbors ----
    const float scale = 1.0f / sqrtf((float)DH);
    float agg[D];
    #pragma unroll
    for (int h = 0; h < NHEADS; h++) {
        float lg[KNN];
        #pragma unroll
        for (int kk = 0; kk < KNN; kk++) {
            const float4* kr = reinterpret_cast<const float4*>(sK + topi[kk]*DPAD + h*DH);
            float s = 0.f;
            #pragma unroll
            for (int d4 = 0; d4 < DH/4; d4++) {
                float4 kv = kr[d4];
                s += q[h*DH+4*d4]*kv.x + q[h*DH+4*d4+1]*kv.y + q[h*DH+4*d4+2]*kv.z + q[h*DH+4*d4+3]*kv.w;
            }
            lg[kk] = s * scale;
        }
        float mx = lg[0];
        #pragma unroll
        for (int kk = 1; kk < KNN; kk++) mx = fmaxf(mx, lg[kk]);
        float den = 0.f;
        #pragma unroll
        for (int kk = 0; kk < KNN; kk++) { lg[kk] = expf(lg[kk] - mx); den += lg[kk]; }
        const float inv = 1.0f / den;

        float ah[DH];
        #pragma unroll
        for (int dd = 0; dd < DH; dd++) ah[dd] = 0.f;
        #pragma unroll
        for (int kk = 0; kk < KNN; kk++) {
            const float w = lg[kk];
            const float4* vr = reinterpret_cast<const float4*>(sV + topi[kk]*DPAD + h*DH);
            #pragma unroll
            for (int d4 = 0; d4 < DH/4; d4++) {
                float4 vv = vr[d4];
                ah[4*d4]+=w*vv.x; ah[4*d4+1]+=w*vv.y; ah[4*d4+2]+=w*vv.z; ah[4*d4+3]+=w*vv.w;
            }
        }
        #pragma unroll
        for (int dd = 0; dd < DH; dd++) agg[h*DH+dd] = ah[dd]*inv;
    }

    if (OPT2) {
        __syncthreads();   // Wo overlay loaded (loc already in registers)
    }

    // ---- phase E: concat([local, agg]) @ Wo + bo, pixel_shuffle scatter ----
    #pragma unroll 1
    for (int cog = 0; cog < COUT; cog++) {
        float o0 = sBo[4*cog+0], o1 = sBo[4*cog+1], o2 = sBo[4*cog+2], o3 = sBo[4*cog+3];
        #pragma unroll
        for (int rr = 0; rr < R; rr++) {
            const float lv = loc[rr];
            const float4 w = reinterpret_cast<const float4*>(sWo + rr*CO)[cog];
            o0 += lv*w.x; o1 += lv*w.y; o2 += lv*w.z; o3 += lv*w.w;
        }
        #pragma unroll
        for (int dd = 0; dd < D; dd++) {
            const float av = agg[dd];
            const float4 w = reinterpret_cast<const float4*>(sWo + (R+dd)*CO)[cog];
            o0 += av*w.x; o1 += av*w.y; o2 += av*w.z; o3 += av*w.w;
        }
        if (Ahi) {
            // flat fc-input index: f = cog*1024 + (2i+si)*32 + (2j+sj)
            const size_t base = (size_t)b*32768 + (size_t)cog*1024 + (size_t)(2*i)*32 + 2*j;
            __half h0=__float2half_rn(o0), h1=__float2half_rn(o1);
            __half h2=__float2half_rn(o2), h3=__float2half_rn(o3);
            __half l0=__float2half_rn(o0-__half2float(h0));
            __half l1=__float2half_rn(o1-__half2float(h1));
            __half l2=__float2half_rn(o2-__half2float(h2));
            __half l3=__float2half_rn(o3-__half2float(h3));
            __half2 ph; ph.x=h0; ph.y=h1;
            __half2 pl; pl.x=l0; pl.y=l1;
            *reinterpret_cast<__half2*>(Ahi + base) = ph;
            *reinterpret_cast<__half2*>(Alo + base) = pl;
            ph.x=h2; ph.y=h3; pl.x=l2; pl.y=l3;
            *reinterpret_cast<__half2*>(Ahi + base + 32) = ph;
            *reinterpret_cast<__half2*>(Alo + base + 32) = pl;
        } else {
            float* yb = Y + ((size_t)(b*COUT + cog)*32 + 2*i)*32 + 2*j;
            *reinterpret_cast<float2*>(yb)      = make_float2(o0, o1);
            *reinterpret_cast<float2*>(yb + 32) = make_float2(o2, o3);
        }
    }
}

// =================================================================================
// W [32768,1024] fp32 -> transposed fp16 [1024][32768]
// =================================================================================
__global__ void __launch_bounds__(256) wconv_kernel(
    const float* __restrict__ W, __half* __restrict__ Th)
{
    __shared__ float t[32][33];
    const int k0 = blockIdx.x * 32, n0 = blockIdx.y * 32;
    const int tx = threadIdx.x, ty = threadIdx.y;   // (32,8)
    #pragma unroll
    for (int r = 0; r < 4; r++)
        t[ty + 8*r][tx] = W[(size_t)(k0 + ty + 8*r)*1024 + n0 + tx];
    __syncthreads();
    #pragma unroll
    for (int r = 0; r < 4; r++) {
        const int nn = ty + 8*r;
        Th[(size_t)(n0 + nn)*32768 + k0 + tx] = __float2half_rn(t[tx][nn]);
    }
}

// =================================================================================
// fc1 GEMM via mma.sync fp16 (A hi/lo split -> 2 products; W single fp16).
// CTA tile 128x128, 8 warps (warp 32x64), BK=32.
// cp.async 3-buffer pipeline, 2-stage lookahead, 2 CTAs/SM (92KB smem, 128 regs).
// grid = (8 Ntiles, 2 Mtiles, 18 Ksplits) = 288 CTAs, all resident at occ 2.
// =================================================================================
__global__ void __launch_bounds__(256, 2) fc1_mma(
    const __half* __restrict__ Ahi, const __half* __restrict__ Alo,
    const __half* __restrict__ Wh, float* __restrict__ P)
{
    extern __shared__ char sm[];
    constexpr int KT = 32768;
    constexpr uint32_t TILE = 10240;            // 128 rows * 80 B
    constexpr uint32_t BUFS = 3*TILE;           // Ah | Al | Wh

    const int tid = threadIdx.x, wid = tid >> 5, lane = tid & 31;
    const int lr = lane >> 2, lc = lane & 3;
    const int tr = lane & 7, tq = lane >> 3;
    const int wm = wid & 3, wn = wid >> 2;
    const int m0 = blockIdx.y * 128, n0 = blockIdx.x * 128;
    const int ksp = blockIdx.z;
    const int sbase  = (ksp < 16) ? ksp*57 : 912 + (ksp - 16)*56;
    const int nstage = (ksp < 16) ? 57 : 56;

    const uint32_t smb = smem_u32(sm);
    const uint32_t rowA = (uint32_t)((tr + (tq & 1)*8)*80 + (tq >> 1)*16);
    const uint32_t rowB = (uint32_t)((tr + (tq >> 1)*8)*80 + (tq & 1)*16);

    const int r0g = tid >> 2, c0g = (tid & 3)*8;
    const __half* gAh = Ahi + (size_t)(m0 + r0g)*KT + c0g;
    const __half* gAl = Alo + (size_t)(m0 + r0g)*KT + c0g;
    const __half* gW  = Wh  + (size_t)(n0 + r0g)*KT + c0g;
    const size_t row64 = (size_t)64*KT;
    const uint32_t soff0 = (uint32_t)(r0g*80 + (tid & 3)*16);
    const uint32_t soff1 = soff0 + 64*80;

    float acc[2][8][4];
    #pragma unroll
    for (int mt = 0; mt < 2; mt++)
        #pragma unroll
        for (int nt = 0; nt < 8; nt++)
            #pragma unroll
            for (int e = 0; e < 4; e++) acc[mt][nt][e] = 0.f;

    #pragma unroll
    for (int p = 0; p < 2; p++) {
        const uint32_t b = smb + (uint32_t)p*BUFS;
        const int kk = (sbase + p)*32;
        cpa16(b + soff0,          gAh + kk);
        cpa16(b + soff1,          gAh + row64 + kk);
        cpa16(b + TILE + soff0,   gAl + kk);
        cpa16(b + TILE + soff1,   gAl + row64 + kk);
        cpa16(b + 2*TILE + soff0, gW + kk);
        cpa16(b + 2*TILE + soff1, gW + row64 + kk);
        CP_COMMIT();
    }

    int bufc = 0, bufn = 2;
    for (int s = 0; s < nstage; s++) {
        CP_WAIT1();
        __syncthreads();
        if (s + 2 < nstage) {
            const uint32_t b = smb + (uint32_t)bufn*BUFS;
            const int kk = (sbase + s + 2)*32;
            cpa16(b + soff0,          gAh + kk);
            cpa16(b + soff1,          gAh + row64 + kk);
            cpa16(b + TILE + soff0,   gAl + kk);
            cpa16(b + TILE + soff1,   gAl + row64 + kk);
            cpa16(b + 2*TILE + soff0, gW + kk);
            cpa16(b + 2*TILE + soff1, gW + row64 + kk);
            CP_COMMIT();
        }
        const uint32_t base = smb + (uint32_t)bufc*BUFS;
        bufc = (bufc + 1 == 3) ? 0 : bufc + 1;
        bufn = (bufn + 1 == 3) ? 0 : bufn + 1;
        const uint32_t aH = base + (uint32_t)(wm*32)*80 + rowA;
        const uint32_t aL = aH + TILE;
        const uint32_t bB = base + 2*TILE + (uint32_t)(wn*64)*80 + rowB;
        #pragma unroll
        for (int ks = 0; ks < 2; ks++) {
            const uint32_t kb = ks*32;
            uint32_t afh[2][4], afl[2][4], bfr[4][4];
            ldsm4(afh[0], aH + kb);            ldsm4(afh[1], aH + 16*80 + kb);
            ldsm4(afl[0], aL + kb);            ldsm4(afl[1], aL + 16*80 + kb);
            #pragma unroll
            for (int p = 0; p < 4; p++) ldsm4(bfr[p], bB + (uint32_t)(p*16)*80 + kb);
            #pragma unroll
            for (int mt = 0; mt < 2; mt++)
                #pragma unroll
                for (int nt = 0; nt < 8; nt++) {
                    uint32_t* bb = &bfr[nt >> 1][(nt & 1)*2];
                    MMA_F16(acc[mt][nt], afh[mt], bb);
                    MMA_F16(acc[mt][nt], afl[mt], bb);
                }
        }
    }

    float* Pp = P + (size_t)ksp * 262144;
    #pragma unroll
    for (int mt = 0; mt < 2; mt++) {
        const int r = m0 + wm*32 + mt*16 + lr;
        #pragma unroll
        for (int nt = 0; nt < 8; nt++) {
            const int cc = n0 + wn*64 + nt*8 + lc*2;
            *(float2*)(Pp + (size_t)r*1024 + cc)       = make_float2(acc[mt][nt][0], acc[mt][nt][1]);
            *(float2*)(Pp + (size_t)(r + 8)*1024 + cc) = make_float2(acc[mt][nt][2], acc[mt][nt][3]);
        }
    }
}

// fc1 partial reduction + bias + relu
__global__ void fc1_reduce(const float* __restrict__ P, const float* __restrict__ Bb,
                           float* __restrict__ O)
{
    const int idx = blockIdx.x * blockDim.x + threadIdx.x;   // 262144 total
    float s = Bb[idx & 1023];
    #pragma unroll
    for (int sp = 0; sp < 18; sp++) s += P[sp*262144 + idx];
    O[idx] = fmaxf(s, 0.f);
}

// fc2: [256,1024] @ [1024,10] + b
__global__ void fc2_kernel(const float* __restrict__ H, const float* __restrict__ W,
                           const float* __restrict__ Bb, float* __restrict__ out)
{
    const int b = blockIdx.x, tid = threadIdx.x;
    float acc[10];
    #pragma unroll
    for (int o = 0; o < 10; o++) acc[o] = 0.f;
    for (int k = tid; k < 1024; k += 128) {
        const float hv = H[b*1024 + k];
        const float* wr = W + k*10;
        #pragma unroll
        for (int o = 0; o < 10; o++) acc[o] += hv * wr[o];
    }
    __shared__ float red[4][10];
    #pragma unroll
    for (int o = 0; o < 10; o++) {
        #pragma unroll
        for (int off = 16; off; off >>= 1)
            acc[o] += __shfl_down_sync(0xffffffffu, acc[o], off);
    }
    if ((tid & 31) == 0) {
        #pragma unroll
        for (int o = 0; o < 10; o++) red[tid >> 5][o] = acc[o];
    }
    __syncthreads();
    if (tid < 10)
        out[b*10 + tid] = Bb[tid] + red[0][tid] + red[1][tid] + red[2][tid] + red[3][tid];
}

// =================================================================================
extern "C" void kernel_launch(void* const* d_in, const int* in_sizes, int n_in,
                              void* d_out, int out_size)
{
    const float* x    = (const float*)d_in[0];
    const float* w1c  = (const float*)d_in[1];
    const float* b1c  = (const float*)d_in[2];
    const float* w1q  = (const float*)d_in[3];
    const float* w1k  = (const float*)d_in[4];
    const float* w1v  = (const float*)d_in[5];
    const float* w1o  = (const float*)d_in[6];
    const float* b1o  = (const float*)d_in[7];
    const float* w2c  = (const float*)d_in[8];
    const float* b2c  = (const float*)d_in[9];
    const float* w2q  = (const float*)d_in[10];
    const float* w2k  = (const float*)d_in[11];
    const float* w2v  = (const float*)d_in[12];
    const float* w2o  = (const float*)d_in[13];
    const float* b2o  = (const float*)d_in[14];
    const float* fc1w = (const float*)d_in[15];
    const float* fc1b = (const float*)d_in[16];
    const float* fc2w = (const float*)d_in[17];
    const float* fc2b = (const float*)d_in[18];
    float* out = (float*)d_out;

    float *h1, *part, *fch;
    __half *ahi, *alo, *wh;
    cudaGetSymbolAddress((void**)&h1,   g_h1);
    cudaGetSymbolAddress((void**)&ahi,  g_Ahi);
    cudaGetSymbolAddress((void**)&alo,  g_Alo);
    cudaGetSymbolAddress((void**)&wh,   g_Wh);
    cudaGetSymbolAddress((void**)&part, g_part);
    cudaGetSymbolAddress((void**)&fch,  g_fc1);

    // layer1: (768 + 2048) proj+Wo + 16 + 64 + 2*256*20 K/V floats
    const int SM1 = (12*16 + 3*12*16 + (16+16)*64 + 16 + 64 + 2*256*(16+4)) * 4;
    // layer2 (overlay): max(8192,8192) + 32 + 128 + 2*256*36 floats = 107136 B -> occ 2
    const int SM2 = (8192 + 32 + 128 + 2*256*(32+4)) * 4;
    const int SMG = 3 * 3 * 10240;   // 92160

    cudaFuncSetAttribute(attn_kernel<3,12,16,16,64,2,0>,
                         cudaFuncAttributeMaxDynamicSharedMemorySize, SM1);
    cudaFuncSetAttribute(attn_kernel<16,64,32,32,128,2,1>,
                         cudaFuncAttributeMaxDynamicSharedMemorySize, SM2);
    cudaFuncSetAttribute(fc1_mma,
                         cudaFuncAttributeMaxDynamicSharedMemorySize, SMG);

    wconv_kernel<<<dim3(1024, 32), dim3(32, 8)>>>(fc1w, wh);
    attn_kernel<3,12,16,16,64,2,0><<<256, 256, SM1>>>(x,  w1c, b1c, w1q, w1k, w1v, w1o, b1o,
                                                  h1, nullptr, nullptr);
    attn_kernel<16,64,32,32,128,2,1><<<256, 256, SM2>>>(h1, w2c, b2c, w2q, w2k, w2v, w2o, b2o,
                                                  nullptr, ahi, alo);
    fc1_mma<<<dim3(8, 2, 18), 256, SMG>>>(ahi, alo, wh, part);
    fc1_reduce<<<1024, 256>>>(part, fc1b, fch);
    fc2_kernel<<<256, 128>>>(fch, fc2w, fc2b, out);
}

// round 13
// speedup vs baseline: 1.7665x; 1.0162x over previous
#include <cuda_runtime.h>
#include <cuda_bf16.h>
#include <cuda_fp16.h>
#include <cstdint>
#include <stdint.h>
#include <math.h>

// ---------------- scratch (device globals; no allocation allowed) ----------------
__device__ float g_h1[256*16*32*32];        // layer1 output [B,16,32,32]
__device__ __half g_Ahi[256*32768];         // fc input, fp16 hi
__device__ __half g_Alo[256*32768];         // fc input, fp16 lo residual
__device__ __half g_Wh[1024ull*32768];      // fc1 weight TRANSPOSED [N,K], fp16
__device__ float g_part[18*256*1024];       // fc1 split-K partials
__device__ float g_fc1[256*1024];           // fc1 output (post relu)

__device__ __forceinline__ uint32_t smem_u32(const void* p) {
    uint32_t a;
    asm("{ .reg .u64 t; cvta.to.shared.u64 t, %1; cvt.u32.u64 %0, t; }" : "=r"(a) : "l"(p));
    return a;
}
__device__ __forceinline__ void ldsm4(uint32_t* r, uint32_t addr) {
    asm volatile("ldmatrix.sync.aligned.m8n8.x4.shared.b16 {%0,%1,%2,%3}, [%4];"
                 : "=r"(r[0]), "=r"(r[1]), "=r"(r[2]), "=r"(r[3]) : "r"(addr));
}
__device__ __forceinline__ void cpa16(uint32_t dst, const void* src) {
    asm volatile("cp.async.ca.shared.global [%0], [%1], 16;" :: "r"(dst), "l"(src));
}
#define CP_COMMIT() asm volatile("cp.async.commit_group;" ::: "memory")
#define CP_WAIT1()  asm volatile("cp.async.wait_group 1;" ::: "memory")
#define MMA_F16(d, a, bb)                                                                      \
    asm volatile("mma.sync.aligned.m16n8k16.row.col.f32.f16.f16.f32 "                          \
        "{%0,%1,%2,%3}, {%4,%5,%6,%7}, {%8,%9}, {%0,%1,%2,%3};"                                \
        : "+f"((d)[0]), "+f"((d)[1]), "+f"((d)[2]), "+f"((d)[3])                               \
        : "r"((a)[0]), "r"((a)[1]), "r"((a)[2]), "r"((a)[3]), "r"((bb)[0]), "r"((bb)[1]))

// =================================================================================
// Fused ConvNN-branch attention layer. grid = B, block = 256 (one thread/token).
// If Ahi/Alo non-null (layer 2), emits fp16 hi/lo split of output instead of fp32.
// OPT2=1 (layer 2): Wo overlaid on projection weights AFTER phase B; q and loc are
// computed in phase B and carried in registers (nothing reads proj weights later).
// =================================================================================
template<int CIN, int CU, int R, int D, int CO, int OCC, int OPT2>
__global__ void __launch_bounds__(256, OCC) attn_kernel(
    const float* __restrict__ X,
    const float* __restrict__ Wc, const float* __restrict__ Bc,
    const float* __restrict__ Wq, const float* __restrict__ Wk, const float* __restrict__ Wv,
    const float* __restrict__ Wo, const float* __restrict__ Bo,
    float* __restrict__ Y, __half* __restrict__ Ahi, __half* __restrict__ Alo)
{
    constexpr int NTOK = 256;
    constexpr int NHEADS = 4;
    constexpr int DH = D / NHEADS;
    constexpr int KNN = 9;
    constexpr int DPAD = D + 4;
    constexpr int COUT = CO / 4;
    constexpr int PROJ = CU*R + 3*CU*D;
    constexpr int WOSZ = (R + D)*CO;
    constexpr int REG0 = OPT2 ? (PROJ > WOSZ ? PROJ : WOSZ) : (PROJ + WOSZ);

    extern __shared__ float smem[];
    float* sWc = smem;
    float* sWq = sWc + CU*R;
    float* sWk = sWq + CU*D;
    float* sWv = sWk + CU*D;
    float* sWo = OPT2 ? smem : (sWv + CU*D);
    float* sBc = smem + REG0;
    float* sBo = sBc + R;
    float* sK  = sBo + CO;
    float* sV  = sK + NTOK*DPAD;

    const int b = blockIdx.x;
    const int n = threadIdx.x;

    for (int idx = n; idx < CU*R; idx += NTOK) sWc[idx] = Wc[idx];
    for (int idx = n; idx < CU*D; idx += NTOK) { sWq[idx]=Wq[idx]; sWk[idx]=Wk[idx]; sWv[idx]=Wv[idx]; }
    if (!OPT2)
        for (int idx = n; idx < WOSZ; idx += NTOK) sWo[idx] = Wo[idx];
    if (n < R)  sBc[n] = Bc[n];
    if (n < CO) sBo[n] = Bo[n];
    __syncthreads();

    const int i = n >> 4;
    const int j = n & 15;

    float q[D], loc[R];

    if (OPT2) {
        // ---- pass 1: k/v projections only (64 live floats) ----
        {
            float ka[D], va[D];
            #pragma unroll
            for (int dd = 0; dd < D; dd++) { ka[dd]=0.f; va[dd]=0.f; }
            #pragma unroll 4
            for (int c = 0; c < CU; c++) {
                const int ch = c >> 2, si = (c >> 1) & 1, sj = c & 1;
                const float tv = X[((b*CIN + ch)*32 + 2*i + si)*32 + 2*j + sj];
                const float4* wk4 = reinterpret_cast<const float4*>(sWk + c*D);
                const float4* wv4 = reinterpret_cast<const float4*>(sWv + c*D);
                #pragma unroll
                for (int d4 = 0; d4 < D/4; d4++) {
                    float4 w;
                    w = wk4[d4]; ka[4*d4]+=tv*w.x; ka[4*d4+1]+=tv*w.y; ka[4*d4+2]+=tv*w.z; ka[4*d4+3]+=tv*w.w;
                    w = wv4[d4]; va[4*d4]+=tv*w.x; va[4*d4+1]+=tv*w.y; va[4*d4+2]+=tv*w.z; va[4*d4+3]+=tv*w.w;
                }
            }
            #pragma unroll
            for (int d4 = 0; d4 < D/4; d4++) {
                reinterpret_cast<float4*>(sK + n*DPAD)[d4] = make_float4(ka[4*d4],ka[4*d4+1],ka[4*d4+2],ka[4*d4+3]);
                reinterpret_cast<float4*>(sV + n*DPAD)[d4] = make_float4(va[4*d4],va[4*d4+1],va[4*d4+2],va[4*d4+3]);
            }
        }
        // ---- pass 2: q + loc projections (kept in registers through C/D) ----
        #pragma unroll
        for (int dd = 0; dd < D; dd++) q[dd] = 0.f;
        #pragma unroll
        for (int rr = 0; rr < R; rr++) loc[rr] = sBc[rr];
        #pragma unroll 4
        for (int c = 0; c < CU; c++) {
            const int ch = c >> 2, si = (c >> 1) & 1, sj = c & 1;
            const float tv = X[((b*CIN + ch)*32 + 2*i + si)*32 + 2*j + sj];
            const float4* wq4 = reinterpret_cast<const float4*>(sWq + c*D);
            const float4* wc4 = reinterpret_cast<const float4*>(sWc + c*R);
            #pragma unroll
            for (int d4 = 0; d4 < D/4; d4++) {
                float4 w = wq4[d4];
                q[4*d4]+=tv*w.x; q[4*d4+1]+=tv*w.y; q[4*d4+2]+=tv*w.z; q[4*d4+3]+=tv*w.w;
            }
            #pragma unroll
            for (int r4 = 0; r4 < R/4; r4++) {
                float4 w = wc4[r4];
                loc[4*r4]+=tv*w.x; loc[4*r4+1]+=tv*w.y; loc[4*r4+2]+=tv*w.z; loc[4*r4+3]+=tv*w.w;
            }
        }
        #pragma unroll
        for (int rr = 0; rr < R; rr++) loc[rr] = fmaxf(loc[rr], 0.f);
        __syncthreads();   // all proj-weight reads done; K/V visible
        // overlay: reload Wo into region0 (latency hidden behind phases C/D)
        for (int idx = n; idx < WOSZ; idx += NTOK) sWo[idx] = Wo[idx];
    } else {
        float ka[D], va[D];
        #pragma unroll
        for (int dd = 0; dd < D; dd++) { q[dd]=0.f; ka[dd]=0.f; va[dd]=0.f; }
        #pragma unroll
        for (int rr = 0; rr < R; rr++) loc[rr] = sBc[rr];

        #pragma unroll 4
        for (int c = 0; c < CU; c++) {
            const int ch = c >> 2, si = (c >> 1) & 1, sj = c & 1;
            const float tv = X[((b*CIN + ch)*32 + 2*i + si)*32 + 2*j + sj];
            const float4* wq4 = reinterpret_cast<const float4*>(sWq + c*D);
            const float4* wk4 = reinterpret_cast<const float4*>(sWk + c*D);
            const float4* wv4 = reinterpret_cast<const float4*>(sWv + c*D);
            const float4* wc4 = reinterpret_cast<const float4*>(sWc + c*R);
            #pragma unroll
            for (int d4 = 0; d4 < D/4; d4++) {
                float4 w;
                w = wq4[d4]; q[4*d4]+=tv*w.x;  q[4*d4+1]+=tv*w.y;  q[4*d4+2]+=tv*w.z;  q[4*d4+3]+=tv*w.w;
                w = wk4[d4]; ka[4*d4]+=tv*w.x; ka[4*d4+1]+=tv*w.y; ka[4*d4+2]+=tv*w.z; ka[4*d4+3]+=tv*w.w;
                w = wv4[d4]; va[4*d4]+=tv*w.x; va[4*d4+1]+=tv*w.y; va[4*d4+2]+=tv*w.z; va[4*d4+3]+=tv*w.w;
            }
            #pragma unroll
            for (int r4 = 0; r4 < R/4; r4++) {
                float4 w = wc4[r4];
                loc[4*r4]+=tv*w.x; loc[4*r4+1]+=tv*w.y; loc[4*r4+2]+=tv*w.z; loc[4*r4+3]+=tv*w.w;
            }
        }
        #pragma unroll
        for (int rr = 0; rr < R; rr++) loc[rr] = fmaxf(loc[rr], 0.f);
        #pragma unroll
        for (int d4 = 0; d4 < D/4; d4++) {
            reinterpret_cast<float4*>(sK + n*DPAD)[d4] = make_float4(ka[4*d4],ka[4*d4+1],ka[4*d4+2],ka[4*d4+3]);
            reinterpret_cast<float4*>(sV + n*DPAD)[d4] = make_float4(va[4*d4],va[4*d4+1],va[4*d4+2],va[4*d4+3]);
        }
        __syncthreads();
    }

    // ---- phase C: full-d sim over all tokens + streaming top-9 ----
    float topv[KNN]; int topi[KNN];
    #pragma unroll
    for (int kk = 0; kk < KNN; kk++) { topv[kk] = -1e30f; topi[kk] = 0; }

    for (int m = 0; m < NTOK; m++) {
        const float4* kp = reinterpret_cast<const float4*>(sK + m*DPAD);
        float dot = 0.f;
        #pragma unroll
        for (int d4 = 0; d4 < D/4; d4++) {
            float4 kv = kp[d4];
            dot += q[4*d4]*kv.x + q[4*d4+1]*kv.y + q[4*d4+2]*kv.z + q[4*d4+3]*kv.w;
        }
        if (dot > topv[KNN-1]) {
            topv[KNN-1] = dot; topi[KNN-1] = m;
            #pragma unroll
            for (int jj = KNN-1; jj > 0; --jj) {
                if (topv[jj] > topv[jj-1]) {
                    float tv_ = topv[jj]; topv[jj] = topv[jj-1]; topv[jj-1] = tv_;
                    int   ti_ = topi[jj]; topi[jj] = topi[jj-1]; topi[jj-1] = ti_;
                }
            }
        }
    }

    // ---- phase D: per-head softmax attention over 9 neighbors ----
    const float scale = 1.0f / sqrtf((float)DH);
    float agg[D];
    #pragma unroll
    for (int h = 0; h < NHEADS; h++) {
        float lg[KNN];
        #pragma unroll
        for (int kk = 0; kk < KNN; kk++) {
            const float4* kr = reinterpret_cast<const float4*>(sK + topi[kk]*DPAD + h*DH);
            float s = 0.f;
            #pragma unroll
            for (int d4 = 0; d4 < DH/4; d4++) {
                float4 kv = kr[d4];
                s += q[h*DH+4*d4]*kv.x + q[h*DH+4*d4+1]*kv.y + q[h*DH+4*d4+2]*kv.z + q[h*DH+4*d4+3]*kv.w;
            }
            lg[kk] = s * scale;
        }
        float mx = lg[0];
        #pragma unroll
        for (int kk = 1; kk < KNN; kk++) mx = fmaxf(mx, lg[kk]);
        float den = 0.f;
        #pragma unroll
        for (int kk = 0; kk < KNN; kk++) { lg[kk] = expf(lg[kk] - mx); den += lg[kk]; }
        const float inv = 1.0f / den;

        float ah[DH];
        #pragma unroll
        for (int dd = 0; dd < DH; dd++) ah[dd] = 0.f;
        #pragma unroll
        for (int kk = 0; kk < KNN; kk++) {
            const float w = lg[kk];
            const float4* vr = reinterpret_cast<const float4*>(sV + topi[kk]*DPAD + h*DH);
            #pragma unroll
            for (int d4 = 0; d4 < DH/4; d4++) {
                float4 vv = vr[d4];
                ah[4*d4]+=w*vv.x; ah[4*d4+1]+=w*vv.y; ah[4*d4+2]+=w*vv.z; ah[4*d4+3]+=w*vv.w;
            }
        }
        #pragma unroll
        for (int dd = 0; dd < DH; dd++) agg[h*DH+dd] = ah[dd]*inv;
    }

    if (OPT2) {
        __syncthreads();   // Wo overlay loaded (loc already in registers)
    }

    // ---- phase E: concat([local, agg]) @ Wo + bo, pixel_shuffle scatter ----
    #pragma unroll 1
    for (int cog = 0; cog < COUT; cog++) {
        float o0 = sBo[4*cog+0], o1 = sBo[4*cog+1], o2 = sBo[4*cog+2], o3 = sBo[4*cog+3];
        #pragma unroll
        for (int rr = 0; rr < R; rr++) {
            const float lv = loc[rr];
            const float4 w = reinterpret_cast<const float4*>(sWo + rr*CO)[cog];
            o0 += lv*w.x; o1 += lv*w.y; o2 += lv*w.z; o3 += lv*w.w;
        }
        #pragma unroll
        for (int dd = 0; dd < D; dd++) {
            const float av = agg[dd];
            const float4 w = reinterpret_cast<const float4*>(sWo + (R+dd)*CO)[cog];
            o0 += av*w.x; o1 += av*w.y; o2 += av*w.z; o3 += av*w.w;
        }
        if (Ahi) {
            // flat fc-input index: f = cog*1024 + (2i+si)*32 + (2j+sj)
            const size_t base = (size_t)b*32768 + (size_t)cog*1024 + (size_t)(2*i)*32 + 2*j;
            __half h0=__float2half_rn(o0), h1=__float2half_rn(o1);
            __half h2=__float2half_rn(o2), h3=__float2half_rn(o3);
            __half l0=__float2half_rn(o0-__half2float(h0));
            __half l1=__float2half_rn(o1-__half2float(h1));
            __half l2=__float2half_rn(o2-__half2float(h2));
            __half l3=__float2half_rn(o3-__half2float(h3));
            __half2 ph; ph.x=h0; ph.y=h1;
            __half2 pl; pl.x=l0; pl.y=l1;
            *reinterpret_cast<__half2*>(Ahi + base) = ph;
            *reinterpret_cast<__half2*>(Alo + base) = pl;
            ph.x=h2; ph.y=h3; pl.x=l2; pl.y=l3;
            *reinterpret_cast<__half2*>(Ahi + base + 32) = ph;
            *reinterpret_cast<__half2*>(Alo + base + 32) = pl;
        } else {
            float* yb = Y + ((size_t)(b*COUT + cog)*32 + 2*i)*32 + 2*j;
            *reinterpret_cast<float2*>(yb)      = make_float2(o0, o1);
            *reinterpret_cast<float2*>(yb + 32) = make_float2(o2, o3);
        }
    }
}

// =================================================================================
// W [32768,1024] fp32 -> transposed fp16 [1024][32768]
// =================================================================================
__global__ void __launch_bounds__(256) wconv_kernel(
    const float* __restrict__ W, __half* __restrict__ Th)
{
    __shared__ float t[32][33];
    const int k0 = blockIdx.x * 32, n0 = blockIdx.y * 32;
    const int tx = threadIdx.x, ty = threadIdx.y;   // (32,8)
    #pragma unroll
    for (int r = 0; r < 4; r++)
        t[ty + 8*r][tx] = W[(size_t)(k0 + ty + 8*r)*1024 + n0 + tx];
    __syncthreads();
    #pragma unroll
    for (int r = 0; r < 4; r++) {
        const int nn = ty + 8*r;
        Th[(size_t)(n0 + nn)*32768 + k0 + tx] = __float2half_rn(t[tx][nn]);
    }
}

// =================================================================================
// fc1 GEMM via mma.sync fp16 (A hi/lo split -> 2 products; W single fp16).
// CTA tile 128x128, 8 warps (warp 32x64), BK=32.
// cp.async 3-buffer pipeline, 2-stage lookahead, 2 CTAs/SM (92KB smem, 128 regs).
// grid = (8 Ntiles, 2 Mtiles, 18 Ksplits) = 288 CTAs, all resident at occ 2.
// =================================================================================
__global__ void __launch_bounds__(256, 2) fc1_mma(
    const __half* __restrict__ Ahi, const __half* __restrict__ Alo,
    const __half* __restrict__ Wh, float* __restrict__ P)
{
    extern __shared__ char sm[];
    constexpr int KT = 32768;
    constexpr uint32_t TILE = 10240;            // 128 rows * 80 B
    constexpr uint32_t BUFS = 3*TILE;           // Ah | Al | Wh

    const int tid = threadIdx.x, wid = tid >> 5, lane = tid & 31;
    const int lr = lane >> 2, lc = lane & 3;
    const int tr = lane & 7, tq = lane >> 3;
    const int wm = wid & 3, wn = wid >> 2;
    const int m0 = blockIdx.y * 128, n0 = blockIdx.x * 128;
    const int ksp = blockIdx.z;
    const int sbase  = (ksp < 16) ? ksp*57 : 912 + (ksp - 16)*56;
    const int nstage = (ksp < 16) ? 57 : 56;

    const uint32_t smb = smem_u32(sm);
    const uint32_t rowA = (uint32_t)((tr + (tq & 1)*8)*80 + (tq >> 1)*16);
    const uint32_t rowB = (uint32_t)((tr + (tq >> 1)*8)*80 + (tq & 1)*16);

    const int r0g = tid >> 2, c0g = (tid & 3)*8;
    const __half* gAh = Ahi + (size_t)(m0 + r0g)*KT + c0g;
    const __half* gAl = Alo + (size_t)(m0 + r0g)*KT + c0g;
    const __half* gW  = Wh  + (size_t)(n0 + r0g)*KT + c0g;
    const size_t row64 = (size_t)64*KT;
    const uint32_t soff0 = (uint32_t)(r0g*80 + (tid & 3)*16);
    const uint32_t soff1 = soff0 + 64*80;

    float acc[2][8][4];
    #pragma unroll
    for (int mt = 0; mt < 2; mt++)
        #pragma unroll
        for (int nt = 0; nt < 8; nt++)
            #pragma unroll
            for (int e = 0; e < 4; e++) acc[mt][nt][e] = 0.f;

    #pragma unroll
    for (int p = 0; p < 2; p++) {
        const uint32_t b = smb + (uint32_t)p*BUFS;
        const int kk = (sbase + p)*32;
        cpa16(b + soff0,          gAh + kk);
        cpa16(b + soff1,          gAh + row64 + kk);
        cpa16(b + TILE + soff0,   gAl + kk);
        cpa16(b + TILE + soff1,   gAl + row64 + kk);
        cpa16(b + 2*TILE + soff0, gW + kk);
        cpa16(b + 2*TILE + soff1, gW + row64 + kk);
        CP_COMMIT();
    }

    int bufc = 0, bufn = 2;
    for (int s = 0; s < nstage; s++) {
        CP_WAIT1();
        __syncthreads();
        if (s + 2 < nstage) {
            const uint32_t b = smb + (uint32_t)bufn*BUFS;
            const int kk = (sbase + s + 2)*32;
            cpa16(b + soff0,          gAh + kk);
            cpa16(b + soff1,          gAh + row64 + kk);
            cpa16(b + TILE + soff0,   gAl + kk);
            cpa16(b + TILE + soff1,   gAl + row64 + kk);
            cpa16(b + 2*TILE + soff0, gW + kk);
            cpa16(b + 2*TILE + soff1, gW + row64 + kk);
            CP_COMMIT();
        }
        const uint32_t base = smb + (uint32_t)bufc*BUFS;
        bufc = (bufc + 1 == 3) ? 0 : bufc + 1;
        bufn = (bufn + 1 == 3) ? 0 : bufn + 1;
        const uint32_t aH = base + (uint32_t)(wm*32)*80 + rowA;
        const uint32_t aL = aH + TILE;
        const uint32_t bB = base + 2*TILE + (uint32_t)(wn*64)*80 + rowB;
        #pragma unroll
        for (int ks = 0; ks < 2; ks++) {
            const uint32_t kb = ks*32;
            uint32_t afh[2][4], afl[2][4], bfr[4][4];
            ldsm4(afh[0], aH + kb);            ldsm4(afh[1], aH + 16*80 + kb);
            ldsm4(afl[0], aL + kb);            ldsm4(afl[1], aL + 16*80 + kb);
            #pragma unroll
            for (int p = 0; p < 4; p++) ldsm4(bfr[p], bB + (uint32_t)(p*16)*80 + kb);
            #pragma unroll
            for (int mt = 0; mt < 2; mt++)
                #pragma unroll
                for (int nt = 0; nt < 8; nt++) {
                    uint32_t* bb = &bfr[nt >> 1][(nt & 1)*2];
                    MMA_F16(acc[mt][nt], afh[mt], bb);
                    MMA_F16(acc[mt][nt], afl[mt], bb);
                }
        }
    }

    float* Pp = P + (size_t)ksp * 262144;
    #pragma unroll
    for (int mt = 0; mt < 2; mt++) {
        const int r = m0 + wm*32 + mt*16 + lr;
        #pragma unroll
        for (int nt = 0; nt < 8; nt++) {
            const int cc = n0 + wn*64 + nt*8 + lc*2;
            *(float2*)(Pp + (size_t)r*1024 + cc)       = make_float2(acc[mt][nt][0], acc[mt][nt][1]);
            *(float2*)(Pp + (size_t)(r + 8)*1024 + cc) = make_float2(acc[mt][nt][2], acc[mt][nt][3]);
        }
    }
}

// fc1 partial reduction + bias + relu
__global__ void fc1_reduce(const float* __restrict__ P, const float* __restrict__ Bb,
                           float* __restrict__ O)
{
    const int idx = blockIdx.x * blockDim.x + threadIdx.x;   // 262144 total
    float s = Bb[idx & 1023];
    #pragma unroll
    for (int sp = 0; sp < 18; sp++) s += P[sp*262144 + idx];
    O[idx] = fmaxf(s, 0.f);
}

// fc2: [256,1024] @ [1024,10] + b
__global__ void fc2_kernel(const float* __restrict__ H, const float* __restrict__ W,
                           const float* __restrict__ Bb, float* __restrict__ out)
{
    const int b = blockIdx.x, tid = threadIdx.x;
    float acc[10];
    #pragma unroll
    for (int o = 0; o < 10; o++) acc[o] = 0.f;
    for (int k = tid; k < 1024; k += 128) {
        const float hv = H[b*1024 + k];
        const float* wr = W + k*10;
        #pragma unroll
        for (int o = 0; o < 10; o++) acc[o] += hv * wr[o];
    }
    __shared__ float red[4][10];
    #pragma unroll
    for (int o = 0; o < 10; o++) {
        #pragma unroll
        for (int off = 16; off; off >>= 1)
            acc[o] += __shfl_down_sync(0xffffffffu, acc[o], off);
    }
    if ((tid & 31) == 0) {
        #pragma unroll
        for (int o = 0; o < 10; o++) red[tid >> 5][o] = acc[o];
    }
    __syncthreads();
    if (tid < 10)
        out[b*10 + tid] = Bb[tid] + red[0][tid] + red[1][tid] + red[2][tid] + red[3][tid];
}

// =================================================================================
extern "C" void kernel_launch(void* const* d_in, const int* in_sizes, int n_in,
                              void* d_out, int out_size)
{
    const float* x    = (const float*)d_in[0];
    const float* w1c  = (const float*)d_in[1];
    const float* b1c  = (const float*)d_in[2];
    const float* w1q  = (const float*)d_in[3];
    const float* w1k  = (const float*)d_in[4];
    const float* w1v  = (const float*)d_in[5];
    const float* w1o  = (const float*)d_in[6];
    const float* b1o  = (const float*)d_in[7];
    const float* w2c  = (const float*)d_in[8];
    const float* b2c  = (const float*)d_in[9];
    const float* w2q  = (const float*)d_in[10];
    const float* w2k  = (const float*)d_in[11];
    const float* w2v  = (const float*)d_in[12];
    const float* w2o  = (const float*)d_in[13];
    const float* b2o  = (const float*)d_in[14];
    const float* fc1w = (const float*)d_in[15];
    const float* fc1b = (const float*)d_in[16];
    const float* fc2w = (const float*)d_in[17];
    const float* fc2b = (const float*)d_in[18];
    float* out = (float*)d_out;

    float *h1, *part, *fch;
    __half *ahi, *alo, *wh;
    cudaGetSymbolAddress((void**)&h1,   g_h1);
    cudaGetSymbolAddress((void**)&ahi,  g_Ahi);
    cudaGetSymbolAddress((void**)&alo,  g_Alo);
    cudaGetSymbolAddress((void**)&wh,   g_Wh);
    cudaGetSymbolAddress((void**)&part, g_part);
    cudaGetSymbolAddress((void**)&fch,  g_fc1);

    // layer1: (768 + 2048) proj+Wo + 16 + 64 + 2*256*20 K/V floats
    const int SM1 = (12*16 + 3*12*16 + (16+16)*64 + 16 + 64 + 2*256*(16+4)) * 4;
    // layer2 (overlay): max(8192,8192) + 32 + 128 + 2*256*36 floats = 107136 B -> occ 2
    const int SM2 = (8192 + 32 + 128 + 2*256*(32+4)) * 4;
    const int SMG = 3 * 3 * 10240;   // 92160

    cudaFuncSetAttribute(attn_kernel<3,12,16,16,64,2,0>,
                         cudaFuncAttributeMaxDynamicSharedMemorySize, SM1);
    cudaFuncSetAttribute(attn_kernel<16,64,32,32,128,2,1>,
                         cudaFuncAttributeMaxDynamicSharedMemorySize, SM2);
    cudaFuncSetAttribute(fc1_mma,
                         cudaFuncAttributeMaxDynamicSharedMemorySize, SMG);

    // ---- fork-join: wconv (DRAM-bound) overlaps attn1+attn2 (compute-bound) ----
    // Handles are created per call and intentionally not destroyed (host-side only,
    // a handful of kernel_launch invocations total; destroy-during-capture is UB).
    cudaStream_t s1;
    cudaStreamCreateWithFlags(&s1, cudaStreamNonBlocking);
    cudaEvent_t e0, e1;
    cudaEventCreateWithFlags(&e0, cudaEventDisableTiming);
    cudaEventCreateWithFlags(&e1, cudaEventDisableTiming);

    cudaEventRecord(e0, 0);                 // fork from legacy stream
    cudaStreamWaitEvent(s1, e0, 0);
    wconv_kernel<<<dim3(1024, 32), dim3(32, 8), 0, s1>>>(fc1w, wh);
    cudaEventRecord(e1, s1);

    attn_kernel<3,12,16,16,64,2,0><<<256, 256, SM1>>>(x,  w1c, b1c, w1q, w1k, w1v, w1o, b1o,
                                                  h1, nullptr, nullptr);
    attn_kernel<16,64,32,32,128,2,1><<<256, 256, SM2>>>(h1, w2c, b2c, w2q, w2k, w2v, w2o, b2o,
                                                  nullptr, ahi, alo);

    cudaStreamWaitEvent(0, e1, 0);          // join: fc1_mma needs Wh + Ahi/Alo
    fc1_mma<<<dim3(8, 2, 18), 256, SMG>>>(ahi, alo, wh, part);
    fc1_reduce<<<1024, 256>>>(part, fc1b, fch);
    fc2_kernel<<<256, 128>>>(fch, fc2w, fc2b, out);
}